// round 7
// baseline (speedup 1.0000x reference)
#include <cuda_runtime.h>
#include <math.h>
#include <stdint.h>

// Problem dims
#define DIM     768
#define HEADS   12
#define HD      64
#define HIDDEN  3072
#define SEQ     1024
#define BATCHN  8
#define TOK     (BATCHN*SEQ)   // 8192
#define QKVDIM  (3*DIM)        // 2304
#define NBH     (BATCHN*HEADS) // 96

// GEMM tiling
#define BK       32
#define KSTRIDE  36                       // 32 + 4 pad: bank = 4*gid + qid, all distinct
#define STAGE_F  (128 * KSTRIDE)          // floats per (A or W) stage
#define GEMM_SMEM (2 * 2 * STAGE_F * 4)   // 73728 B -> 3 CTAs/SM = 216KB

// flash smem strides (floats)
#define QK_STRIDE 68
#define V_STRIDE  72
#define P_STRIDE  132
#define FLASH_SMEM ((128*QK_STRIDE + 128*QK_STRIDE + 128*V_STRIDE + 8*16*P_STRIDE) * 4)

// ---------------- scratch ----------------
__device__ float g_h1[TOK*DIM];
__device__ float g_qkv[(size_t)TOK*QKVDIM];
__device__ float g_olin[TOK*DIM];
__device__ float g_x2[TOK*DIM];
__device__ float g_h2[TOK*DIM];
__device__ float g_h3[(size_t)TOK*HIDDEN];

// ---------------- helpers ----------------
__device__ __forceinline__ unsigned f2tf(float x) {
    unsigned y; asm("cvt.rna.tf32.f32 %0, %1;" : "=r"(y) : "f"(x)); return y;
}
__device__ __forceinline__ float tf32f(float x) { return __uint_as_float(f2tf(x)); }
__device__ __forceinline__ void sts_tf32(float* dst, float4 v) {
    float4 o;
    o.x = tf32f(v.x); o.y = tf32f(v.y); o.z = tf32f(v.z); o.w = tf32f(v.w);
    *(float4*)dst = o;
}
__device__ __forceinline__ void mma8(float* d, const float* a, const float* b) {
    asm volatile(
        "mma.sync.aligned.m16n8k8.row.col.f32.tf32.tf32.f32 "
        "{%0,%1,%2,%3}, {%4,%5,%6,%7}, {%8,%9}, {%0,%1,%2,%3};"
        : "+f"(d[0]), "+f"(d[1]), "+f"(d[2]), "+f"(d[3])
        : "r"(__float_as_uint(a[0])), "r"(__float_as_uint(a[1])),
          "r"(__float_as_uint(a[2])), "r"(__float_as_uint(a[3])),
          "r"(__float_as_uint(b[0])), "r"(__float_as_uint(b[1])));
}
__device__ __forceinline__ float gelu1(float x) {
    return 0.5f * x * (1.f + erff(x * 0.70710678118654752f));
}
__device__ __forceinline__ void cp16(float* dst, const float* src) {
    unsigned d = (unsigned)__cvta_generic_to_shared(dst);
    asm volatile("cp.async.cg.shared.global [%0], [%1], 16;\n" :: "r"(d), "l"(src));
}
__device__ __forceinline__ void cp_commit() {
    asm volatile("cp.async.commit_group;\n");
}
template<int N>
__device__ __forceinline__ void cp_wait() {
    asm volatile("cp.async.wait_group %0;\n" :: "n"(N));
}

// ---------------- LayerNorm ----------------
__global__ void ln_kernel(const float* __restrict__ in,
                          const float* __restrict__ gam,
                          const float* __restrict__ bet,
                          float* __restrict__ out) {
    int row = blockIdx.x;
    int t = threadIdx.x;
    const float* x = in + (size_t)row * DIM;
    float v0 = x[t], v1 = x[t + 256], v2 = x[t + 512];
    float s  = v0 + v1 + v2;
    float sq = v0*v0 + v1*v1 + v2*v2;
    __shared__ float redS[8], redQ[8];
    #pragma unroll
    for (int o = 16; o > 0; o >>= 1) {
        s  += __shfl_xor_sync(0xffffffffu, s,  o);
        sq += __shfl_xor_sync(0xffffffffu, sq, o);
    }
    if ((t & 31) == 0) { redS[t >> 5] = s; redQ[t >> 5] = sq; }
    __syncthreads();
    if (t < 32) {
        float s2 = (t < 8) ? redS[t] : 0.f;
        float q2 = (t < 8) ? redQ[t] : 0.f;
        #pragma unroll
        for (int o = 4; o > 0; o >>= 1) {
            s2 += __shfl_xor_sync(0xffffffffu, s2, o);
            q2 += __shfl_xor_sync(0xffffffffu, q2, o);
        }
        if (t == 0) { redS[0] = s2; redQ[0] = q2; }
    }
    __syncthreads();
    float mu  = redS[0] * (1.0f / DIM);
    float var = redQ[0] * (1.0f / DIM) - mu * mu;
    float inv = rsqrtf(var + 1e-5f);
    float* o = out + (size_t)row * DIM;
    o[t]       = (v0 - mu) * inv * gam[t]       + bet[t];
    o[t + 256] = (v1 - mu) * inv * gam[t + 256] + bet[t + 256];
    o[t + 512] = (v2 - mu) * inv * gam[t + 512] + bet[t + 512];
}

// ---------------- TF32 MMA GEMM (TN), 128 thr, warp 64x64, 3 CTAs/SM ----------------
enum { EPI_BIAS = 1, EPI_BIAS_RES = 2, EPI_BIAS_GELU = 3 };

template<int EPI>
__global__ __launch_bounds__(128, 3)
void mma_tn_kernel(const float* __restrict__ A, int lda,
                   const float* __restrict__ W, int ldw,
                   float* __restrict__ C, int ldc, int K,
                   const float* __restrict__ bias,
                   const float* __restrict__ res, int ldres) {
    extern __shared__ float smp[];
    // layout: [stage][A(128*36) | W(128*36)]
    const int m0 = blockIdx.y * 128, n0 = blockIdx.x * 128;
    const int tid  = threadIdx.x;
    const int lane = tid & 31;
    const int warp = tid >> 5;
    const int m0w  = (warp >> 1) * 64;   // 2 warps along M
    const int n0w  = (warp & 1) * 64;    // 2 warps along N
    const int gid  = lane >> 2;
    const int qid  = lane & 3;

    // cp.async mapping: 1024 16B-chunks per (A|W) stage, 128 threads -> 8 each
    const int crow0 = tid >> 3;          // 0..15 base row
    const int cgr   = tid & 7;           // 16B group within row (0..7)

    float acc[4][8][4];
    #pragma unroll
    for (int i = 0; i < 4; i++)
        #pragma unroll
        for (int j = 0; j < 8; j++)
            #pragma unroll
            for (int r = 0; r < 4; r++) acc[i][j][r] = 0.f;

    const int nch = K / BK;

    // stage loader
    auto load_chunk = [&](int j) {
        float* as = smp + (j & 1) * 2 * STAGE_F;
        float* ws = as + STAGE_F;
        const float* Aj = A + (size_t)m0 * lda + j * BK + cgr * 4;
        const float* Wj = W + (size_t)n0 * ldw + j * BK + cgr * 4;
        #pragma unroll
        for (int r = 0; r < 8; r++) {
            int row = crow0 + r * 16;
            cp16(&as[row * KSTRIDE + cgr * 4], Aj + (size_t)row * lda);
            cp16(&ws[row * KSTRIDE + cgr * 4], Wj + (size_t)row * ldw);
        }
    };

    load_chunk(0);
    cp_commit();

    for (int i = 0; i < nch; i++) {
        cp_wait<0>();
        __syncthreads();     // chunk i visible to all; all done reading buf (i+1)&1

        if (i + 1 < nch) {
            load_chunk(i + 1);
            cp_commit();
        }

        const float* As = smp + (i & 1) * 2 * STAGE_F;
        const float* Ws = As + STAGE_F;
        #pragma unroll
        for (int ks = 0; ks < 4; ks++) {
            const int c = ks * 8 + qid;
            float af[4][4];
            #pragma unroll
            for (int mt = 0; mt < 4; mt++) {
                const float* p = &As[(m0w + mt * 16 + gid) * KSTRIDE + c];
                af[mt][0] = p[0];
                af[mt][1] = p[8 * KSTRIDE];
                af[mt][2] = p[4];
                af[mt][3] = p[8 * KSTRIDE + 4];
            }
            // bf loaded per n-tile: keeps live regs ~160 (no spill at 170 cap)
            #pragma unroll
            for (int nt = 0; nt < 8; nt++) {
                float bf[2];
                const float* p = &Ws[(n0w + nt * 8 + gid) * KSTRIDE + c];
                bf[0] = p[0];
                bf[1] = p[4];
                #pragma unroll
                for (int mt = 0; mt < 4; mt++)
                    mma8(acc[mt][nt], af[mt], bf);
            }
        }
    }

    // epilogue
    #pragma unroll
    for (int mt = 0; mt < 4; mt++) {
        #pragma unroll
        for (int nt = 0; nt < 8; nt++) {
            int row = m0 + m0w + mt * 16 + gid;
            int col = n0 + n0w + nt * 8 + qid * 2;
            float2 v0, v1;
            v0.x = acc[mt][nt][0]; v0.y = acc[mt][nt][1];
            v1.x = acc[mt][nt][2]; v1.y = acc[mt][nt][3];
            {
                float2 bb = *(const float2*)(bias + col);
                v0.x += bb.x; v0.y += bb.y; v1.x += bb.x; v1.y += bb.y;
            }
            if (EPI == EPI_BIAS_RES) {
                float2 r0 = *(const float2*)(res + (size_t)row * ldres + col);
                float2 r1 = *(const float2*)(res + (size_t)(row + 8) * ldres + col);
                v0.x += r0.x; v0.y += r0.y; v1.x += r1.x; v1.y += r1.y;
            }
            if (EPI == EPI_BIAS_GELU) {
                v0.x = gelu1(v0.x); v0.y = gelu1(v0.y);
                v1.x = gelu1(v1.x); v1.y = gelu1(v1.y);
            }
            *(float2*)(C + (size_t)row * ldc + col) = v0;
            *(float2*)(C + (size_t)(row + 8) * ldc + col) = v1;
        }
    }
}

// ---------------- Flash attention (unchanged) ----------------
__global__ __launch_bounds__(256)
void flash_kernel(const float* __restrict__ qkv, float* __restrict__ olin) {
    extern __shared__ float sm[];
    float* Qs = sm;
    float* Ks = Qs + 128 * QK_STRIDE;
    float* Vs = Ks + 128 * QK_STRIDE;
    float* Ps = Vs + 128 * V_STRIDE;

    const int bh = blockIdx.y;
    const int b = bh / HEADS, h = bh % HEADS;
    const int m0 = blockIdx.x * 128;
    const float* Qg = qkv + (size_t)b * SEQ * QKVDIM + h * HD;
    const float* Kg = Qg + DIM;
    const float* Vg = Qg + 2 * DIM;

    const int tid = threadIdx.x, lane = tid & 31, warp = tid >> 5;
    const int gid = lane >> 2, qid = lane & 3;

    #pragma unroll
    for (int i = 0; i < 8; i++) {
        int f = i * 256 + tid;
        int r = f >> 4, c4 = (f & 15) * 4;
        float4 v = *(const float4*)(Qg + (size_t)(m0 + r) * QKVDIM + c4);
        v.x *= 0.125f; v.y *= 0.125f; v.z *= 0.125f; v.w *= 0.125f;
        sts_tf32(&Qs[r * QK_STRIDE + c4], v);
    }
    __syncthreads();

    float qf[8][4];
    #pragma unroll
    for (int kk = 0; kk < 8; kk++) {
        const float* p = &Qs[(warp * 16 + gid) * QK_STRIDE + kk * 8 + qid];
        qf[kk][0] = p[0];
        qf[kk][1] = p[8 * QK_STRIDE];
        qf[kk][2] = p[4];
        qf[kk][3] = p[8 * QK_STRIDE + 4];
    }

    float m_i[2] = {-1e30f, -1e30f};
    float l_i[2] = {0.f, 0.f};
    float oacc[8][4];
    #pragma unroll
    for (int nt = 0; nt < 8; nt++)
        #pragma unroll
        for (int r = 0; r < 4; r++) oacc[nt][r] = 0.f;

    float* Pw = Ps + warp * 16 * P_STRIDE;

    for (int kc = 0; kc < 8; kc++) {
        __syncthreads();
        const float* Kc = Kg + (size_t)(kc * 128) * QKVDIM;
        const float* Vc = Vg + (size_t)(kc * 128) * QKVDIM;
        #pragma unroll
        for (int i = 0; i < 8; i++) {
            int f = i * 256 + tid;
            int r = f >> 4, c4 = (f & 15) * 4;
            float4 kv = *(const float4*)(Kc + (size_t)r * QKVDIM + c4);
            sts_tf32(&Ks[r * QK_STRIDE + c4], kv);
            float4 vv = *(const float4*)(Vc + (size_t)r * QKVDIM + c4);
            sts_tf32(&Vs[r * V_STRIDE + c4], vv);
        }
        __syncthreads();

        float sacc[16][4];
        #pragma unroll
        for (int nt = 0; nt < 16; nt++)
            #pragma unroll
            for (int r = 0; r < 4; r++) sacc[nt][r] = 0.f;
        #pragma unroll
        for (int kk = 0; kk < 8; kk++) {
            #pragma unroll
            for (int nt = 0; nt < 16; nt++) {
                float bf[2];
                const float* p = &Ks[(nt * 8 + gid) * QK_STRIDE + kk * 8 + qid];
                bf[0] = p[0];
                bf[1] = p[4];
                mma8(sacc[nt], qf[kk], bf);
            }
        }

        float mx0 = -1e30f, mx1 = -1e30f;
        #pragma unroll
        for (int nt = 0; nt < 16; nt++) {
            mx0 = fmaxf(mx0, fmaxf(sacc[nt][0], sacc[nt][1]));
            mx1 = fmaxf(mx1, fmaxf(sacc[nt][2], sacc[nt][3]));
        }
        mx0 = fmaxf(mx0, __shfl_xor_sync(0xffffffffu, mx0, 1));
        mx0 = fmaxf(mx0, __shfl_xor_sync(0xffffffffu, mx0, 2));
        mx1 = fmaxf(mx1, __shfl_xor_sync(0xffffffffu, mx1, 1));
        mx1 = fmaxf(mx1, __shfl_xor_sync(0xffffffffu, mx1, 2));

        float mnew0 = fmaxf(m_i[0], mx0);
        float mnew1 = fmaxf(m_i[1], mx1);
        float f0 = __expf(m_i[0] - mnew0);
        float f1 = __expf(m_i[1] - mnew1);
        m_i[0] = mnew0; m_i[1] = mnew1;
        l_i[0] *= f0;   l_i[1] *= f1;
        #pragma unroll
        for (int nt = 0; nt < 8; nt++) {
            oacc[nt][0] *= f0; oacc[nt][1] *= f0;
            oacc[nt][2] *= f1; oacc[nt][3] *= f1;
        }

        float rs0 = 0.f, rs1 = 0.f;
        #pragma unroll
        for (int nt = 0; nt < 16; nt++) {
            float p0 = __expf(sacc[nt][0] - mnew0);
            float p1 = __expf(sacc[nt][1] - mnew0);
            float p2 = __expf(sacc[nt][2] - mnew1);
            float p3 = __expf(sacc[nt][3] - mnew1);
            rs0 += p0 + p1; rs1 += p2 + p3;
            float2 lo; lo.x = tf32f(p0); lo.y = tf32f(p1);
            float2 hi; hi.x = tf32f(p2); hi.y = tf32f(p3);
            *(float2*)&Pw[gid * P_STRIDE + nt * 8 + qid * 2] = lo;
            *(float2*)&Pw[(gid + 8) * P_STRIDE + nt * 8 + qid * 2] = hi;
        }
        rs0 += __shfl_xor_sync(0xffffffffu, rs0, 1);
        rs0 += __shfl_xor_sync(0xffffffffu, rs0, 2);
        rs1 += __shfl_xor_sync(0xffffffffu, rs1, 1);
        rs1 += __shfl_xor_sync(0xffffffffu, rs1, 2);
        l_i[0] += rs0; l_i[1] += rs1;

        __syncwarp();

        #pragma unroll
        for (int kk = 0; kk < 16; kk++) {
            float af[4];
            const float* p = &Pw[gid * P_STRIDE + kk * 8 + qid];
            af[0] = p[0];
            af[1] = p[8 * P_STRIDE];
            af[2] = p[4];
            af[3] = p[8 * P_STRIDE + 4];
            #pragma unroll
            for (int nt = 0; nt < 8; nt++) {
                float bf[2];
                bf[0] = Vs[(kk * 8 + qid) * V_STRIDE + nt * 8 + gid];
                bf[1] = Vs[(kk * 8 + qid + 4) * V_STRIDE + nt * 8 + gid];
                mma8(oacc[nt], af, bf);
            }
        }
        __syncwarp();
    }

    float inv0 = 1.f / l_i[0];
    float inv1 = 1.f / l_i[1];
    float* C = olin + (size_t)b * SEQ * DIM + h * HD;
    int row = m0 + warp * 16 + gid;
    #pragma unroll
    for (int nt = 0; nt < 8; nt++) {
        int col = nt * 8 + qid * 2;
        float2 v0, v1;
        v0.x = oacc[nt][0] * inv0; v0.y = oacc[nt][1] * inv0;
        v1.x = oacc[nt][2] * inv1; v1.y = oacc[nt][3] * inv1;
        *(float2*)(C + (size_t)row * DIM + col) = v0;
        *(float2*)(C + (size_t)(row + 8) * DIM + col) = v1;
    }
}

// ---------------- launch ----------------
extern "C" void kernel_launch(void* const* d_in, const int* in_sizes, int n_in,
                              void* d_out, int out_size) {
    const float* x       = (const float*)d_in[0];
    const float* n1g     = (const float*)d_in[1];
    const float* n1b     = (const float*)d_in[2];
    const float* qkv_w   = (const float*)d_in[3];
    const float* qkv_b   = (const float*)d_in[4];
    const float* proj_w  = (const float*)d_in[5];
    const float* proj_b  = (const float*)d_in[6];
    const float* n2g     = (const float*)d_in[7];
    const float* n2b     = (const float*)d_in[8];
    const float* fc1_w   = (const float*)d_in[9];
    const float* fc1_b   = (const float*)d_in[10];
    const float* fc2_w   = (const float*)d_in[11];
    const float* fc2_b   = (const float*)d_in[12];
    float* out = (float*)d_out;

    float *h1, *qkv, *olin, *x2, *h2, *h3;
    cudaGetSymbolAddress((void**)&h1,   g_h1);
    cudaGetSymbolAddress((void**)&qkv,  g_qkv);
    cudaGetSymbolAddress((void**)&olin, g_olin);
    cudaGetSymbolAddress((void**)&x2,   g_x2);
    cudaGetSymbolAddress((void**)&h2,   g_h2);
    cudaGetSymbolAddress((void**)&h3,   g_h3);

    cudaFuncSetAttribute(mma_tn_kernel<EPI_BIAS>,
                         cudaFuncAttributeMaxDynamicSharedMemorySize, GEMM_SMEM);
    cudaFuncSetAttribute(mma_tn_kernel<EPI_BIAS_RES>,
                         cudaFuncAttributeMaxDynamicSharedMemorySize, GEMM_SMEM);
    cudaFuncSetAttribute(mma_tn_kernel<EPI_BIAS_GELU>,
                         cudaFuncAttributeMaxDynamicSharedMemorySize, GEMM_SMEM);
    cudaFuncSetAttribute(flash_kernel,
                         cudaFuncAttributeMaxDynamicSharedMemorySize, FLASH_SMEM);

    // 1) LN1
    ln_kernel<<<TOK, 256>>>(x, n1g, n1b, h1);
    // 2) QKV = h1 @ qkv_w^T + b
    mma_tn_kernel<EPI_BIAS><<<dim3(QKVDIM/128, TOK/128), 128, GEMM_SMEM>>>(
        h1, DIM, qkv_w, DIM, qkv, QKVDIM, DIM, qkv_b, nullptr, 0);
    // 3) fused attention -> olin
    flash_kernel<<<dim3(SEQ/128, NBH), 256, FLASH_SMEM>>>(qkv, olin);
    // 4) x2 = x + olin @ proj_w^T + b
    mma_tn_kernel<EPI_BIAS_RES><<<dim3(DIM/128, TOK/128), 128, GEMM_SMEM>>>(
        olin, DIM, proj_w, DIM, x2, DIM, DIM, proj_b, x, DIM);
    // 5) LN2
    ln_kernel<<<TOK, 256>>>(x2, n2g, n2b, h2);
    // 6) h3 = gelu(h2 @ fc1_w^T + b)
    mma_tn_kernel<EPI_BIAS_GELU><<<dim3(HIDDEN/128, TOK/128), 128, GEMM_SMEM>>>(
        h2, DIM, fc1_w, DIM, h3, HIDDEN, DIM, fc1_b, nullptr, 0);
    // 7) out = x2 + h3 @ fc2_w^T + b
    mma_tn_kernel<EPI_BIAS_RES><<<dim3(DIM/128, TOK/128), 128, GEMM_SMEM>>>(
        h3, HIDDEN, fc2_w, HIDDEN, out, DIM, HIDDEN, fc2_b, x2, DIM);
}

// round 8
// speedup vs baseline: 1.5082x; 1.5082x over previous
#include <cuda_runtime.h>
#include <cuda_fp16.h>
#include <math.h>
#include <stdint.h>

// Problem dims
#define DIM     768
#define HEADS   12
#define HD      64
#define HIDDEN  3072
#define SEQ     1024
#define BATCHN  8
#define TOK     (BATCHN*SEQ)   // 8192
#define QKVDIM  (3*DIM)        // 2304
#define NBH     (BATCHN*HEADS) // 96

// fp16 GEMM tiling
#define BKH      64                        // k per chunk (halves)
#define HSTRIDE  72                        // halves per smem row (64 + 8 pad) = 36 words
#define STAGE_H  (128 * HSTRIDE)           // halves per (A or W) stage
#define GEMM_SMEM (2 * 2 * STAGE_H * 2)    // 73728 B

// flash smem strides (floats)
#define QK_STRIDE 68
#define V_STRIDE  72
#define P_STRIDE  132
#define FLASH_SMEM ((128*QK_STRIDE + 128*QK_STRIDE + 128*V_STRIDE + 8*16*P_STRIDE) * 4)

// ---------------- scratch ----------------
__device__ __half g_h1h[TOK*DIM];
__device__ __half g_h2h[TOK*DIM];
__device__ __half g_olinh[TOK*DIM];
__device__ __half g_h3h[(size_t)TOK*HIDDEN];
__device__ float  g_qkv[(size_t)TOK*QKVDIM];
__device__ float  g_x2[TOK*DIM];
__device__ __half g_qkvwh[QKVDIM*DIM];
__device__ __half g_projwh[DIM*DIM];
__device__ __half g_fc1wh[HIDDEN*DIM];
__device__ __half g_fc2wh[DIM*HIDDEN];

// ---------------- helpers ----------------
__device__ __forceinline__ unsigned f2tf(float x) {
    unsigned y; asm("cvt.rna.tf32.f32 %0, %1;" : "=r"(y) : "f"(x)); return y;
}
__device__ __forceinline__ float tf32f(float x) { return __uint_as_float(f2tf(x)); }
__device__ __forceinline__ void sts_tf32(float* dst, float4 v) {
    float4 o;
    o.x = tf32f(v.x); o.y = tf32f(v.y); o.z = tf32f(v.z); o.w = tf32f(v.w);
    *(float4*)dst = o;
}
__device__ __forceinline__ void mma8(float* d, const float* a, const float* b) {
    asm volatile(
        "mma.sync.aligned.m16n8k8.row.col.f32.tf32.tf32.f32 "
        "{%0,%1,%2,%3}, {%4,%5,%6,%7}, {%8,%9}, {%0,%1,%2,%3};"
        : "+f"(d[0]), "+f"(d[1]), "+f"(d[2]), "+f"(d[3])
        : "r"(__float_as_uint(a[0])), "r"(__float_as_uint(a[1])),
          "r"(__float_as_uint(a[2])), "r"(__float_as_uint(a[3])),
          "r"(__float_as_uint(b[0])), "r"(__float_as_uint(b[1])));
}
__device__ __forceinline__ void mma16(float* d, const uint32_t* a, uint32_t b0, uint32_t b1) {
    asm volatile(
        "mma.sync.aligned.m16n8k16.row.col.f32.f16.f16.f32 "
        "{%0,%1,%2,%3}, {%4,%5,%6,%7}, {%8,%9}, {%0,%1,%2,%3};"
        : "+f"(d[0]), "+f"(d[1]), "+f"(d[2]), "+f"(d[3])
        : "r"(a[0]), "r"(a[1]), "r"(a[2]), "r"(a[3]), "r"(b0), "r"(b1));
}
__device__ __forceinline__ float gelu1(float x) {
    return 0.5f * x * (1.f + erff(x * 0.70710678118654752f));
}
__device__ __forceinline__ void cp16h(__half* dst, const __half* src) {
    unsigned d = (unsigned)__cvta_generic_to_shared(dst);
    asm volatile("cp.async.cg.shared.global [%0], [%1], 16;\n" :: "r"(d), "l"(src));
}
__device__ __forceinline__ void cp_commit() {
    asm volatile("cp.async.commit_group;\n");
}
template<int N>
__device__ __forceinline__ void cp_wait() {
    asm volatile("cp.async.wait_group %0;\n" :: "n"(N));
}

// ---------------- fp32 -> fp16 converter (weights) ----------------
__global__ void cvt_f2h(const float4* __restrict__ src, __half2* __restrict__ dst, int n4) {
    int i = blockIdx.x * blockDim.x + threadIdx.x;
    if (i < n4) {
        float4 v = src[i];
        dst[2*i]   = __floats2half2_rn(v.x, v.y);
        dst[2*i+1] = __floats2half2_rn(v.z, v.w);
    }
}

// ---------------- LayerNorm (fp32 in, fp16 out) ----------------
__global__ void ln_kernel(const float* __restrict__ in,
                          const float* __restrict__ gam,
                          const float* __restrict__ bet,
                          __half* __restrict__ out) {
    int row = blockIdx.x;
    int t = threadIdx.x;
    const float* x = in + (size_t)row * DIM;
    float v0 = x[t], v1 = x[t + 256], v2 = x[t + 512];
    float s  = v0 + v1 + v2;
    float sq = v0*v0 + v1*v1 + v2*v2;
    __shared__ float redS[8], redQ[8];
    #pragma unroll
    for (int o = 16; o > 0; o >>= 1) {
        s  += __shfl_xor_sync(0xffffffffu, s,  o);
        sq += __shfl_xor_sync(0xffffffffu, sq, o);
    }
    if ((t & 31) == 0) { redS[t >> 5] = s; redQ[t >> 5] = sq; }
    __syncthreads();
    if (t < 32) {
        float s2 = (t < 8) ? redS[t] : 0.f;
        float q2 = (t < 8) ? redQ[t] : 0.f;
        #pragma unroll
        for (int o = 4; o > 0; o >>= 1) {
            s2 += __shfl_xor_sync(0xffffffffu, s2, o);
            q2 += __shfl_xor_sync(0xffffffffu, q2, o);
        }
        if (t == 0) { redS[0] = s2; redQ[0] = q2; }
    }
    __syncthreads();
    float mu  = redS[0] * (1.0f / DIM);
    float var = redQ[0] * (1.0f / DIM) - mu * mu;
    float inv = rsqrtf(var + 1e-5f);
    __half* o = out + (size_t)row * DIM;
    o[t]       = __float2half((v0 - mu) * inv * gam[t]       + bet[t]);
    o[t + 256] = __float2half((v1 - mu) * inv * gam[t + 256] + bet[t + 256]);
    o[t + 512] = __float2half((v2 - mu) * inv * gam[t + 512] + bet[t + 512]);
}

// ---------------- FP16 MMA GEMM (TN): C[M,N] = A[M,K] @ W[N,K]^T ----------------
// 128 thr, CTA 128x128, warp 64x64, m16n8k16, BK=64 chunks, 2-stage cp.async.
enum { EPI_BIAS = 1, EPI_BIAS_RES = 2, EPI_BIAS_GELU = 3 };

template<int EPI, int OUTH>
__global__ __launch_bounds__(128)
void hgemm_tn_kernel(const __half* __restrict__ A, int lda,
                     const __half* __restrict__ W, int ldw,
                     void* __restrict__ Cv, int ldc, int K,
                     const float* __restrict__ bias,
                     const float* __restrict__ res, int ldres) {
    extern __shared__ __half smh[];
    const int m0 = blockIdx.y * 128, n0 = blockIdx.x * 128;
    const int tid  = threadIdx.x;
    const int lane = tid & 31;
    const int warp = tid >> 5;
    const int m0w  = (warp >> 1) * 64;
    const int n0w  = (warp & 1) * 64;
    const int gid  = lane >> 2;
    const int qid  = lane & 3;

    // cp.async mapping: per array 128 rows x 8 x 16B; 128 threads -> 8 per array
    const int crow0 = tid >> 3;          // 0..15
    const int cgr   = tid & 7;           // 0..7 (16B group = 8 halves)

    float acc[4][8][4];
    #pragma unroll
    for (int i = 0; i < 4; i++)
        #pragma unroll
        for (int j = 0; j < 8; j++)
            #pragma unroll
            for (int r = 0; r < 4; r++) acc[i][j][r] = 0.f;

    const int nch = K / BKH;

    auto load_chunk = [&](int j) {
        __half* as = smh + (j & 1) * 2 * STAGE_H;
        __half* ws = as + STAGE_H;
        const __half* Aj = A + (size_t)m0 * lda + j * BKH + cgr * 8;
        const __half* Wj = W + (size_t)n0 * ldw + j * BKH + cgr * 8;
        #pragma unroll
        for (int r = 0; r < 8; r++) {
            int row = crow0 + r * 16;
            cp16h(&as[row * HSTRIDE + cgr * 8], Aj + (size_t)row * lda);
            cp16h(&ws[row * HSTRIDE + cgr * 8], Wj + (size_t)row * ldw);
        }
    };

    load_chunk(0);
    cp_commit();

    for (int i = 0; i < nch; i++) {
        cp_wait<0>();
        __syncthreads();

        if (i + 1 < nch) {
            load_chunk(i + 1);
            cp_commit();
        }

        const __half* As = smh + (i & 1) * 2 * STAGE_H;
        const __half* Ws = As + STAGE_H;
        #pragma unroll
        for (int ks = 0; ks < 4; ks++) {
            const int w0 = ks * 8 + qid;   // 32-bit word index within row
            uint32_t af[4][4];
            #pragma unroll
            for (int mt = 0; mt < 4; mt++) {
                const uint32_t* p0 = (const uint32_t*)(As + (m0w + mt * 16 + gid) * HSTRIDE);
                const uint32_t* p1 = (const uint32_t*)(As + (m0w + mt * 16 + gid + 8) * HSTRIDE);
                af[mt][0] = p0[w0];
                af[mt][1] = p1[w0];
                af[mt][2] = p0[w0 + 4];
                af[mt][3] = p1[w0 + 4];
            }
            #pragma unroll
            for (int nt = 0; nt < 8; nt++) {
                const uint32_t* pb = (const uint32_t*)(Ws + (n0w + nt * 8 + gid) * HSTRIDE);
                uint32_t b0 = pb[w0];
                uint32_t b1 = pb[w0 + 4];
                #pragma unroll
                for (int mt = 0; mt < 4; mt++)
                    mma16(acc[mt][nt], af[mt], b0, b1);
            }
        }
    }

    // epilogue
    #pragma unroll
    for (int mt = 0; mt < 4; mt++) {
        #pragma unroll
        for (int nt = 0; nt < 8; nt++) {
            int row = m0 + m0w + mt * 16 + gid;
            int col = n0 + n0w + nt * 8 + qid * 2;
            float2 v0, v1;
            v0.x = acc[mt][nt][0]; v0.y = acc[mt][nt][1];
            v1.x = acc[mt][nt][2]; v1.y = acc[mt][nt][3];
            {
                float2 bb = *(const float2*)(bias + col);
                v0.x += bb.x; v0.y += bb.y; v1.x += bb.x; v1.y += bb.y;
            }
            if (EPI == EPI_BIAS_RES) {
                float2 r0 = *(const float2*)(res + (size_t)row * ldres + col);
                float2 r1 = *(const float2*)(res + (size_t)(row + 8) * ldres + col);
                v0.x += r0.x; v0.y += r0.y; v1.x += r1.x; v1.y += r1.y;
            }
            if (EPI == EPI_BIAS_GELU) {
                v0.x = gelu1(v0.x); v0.y = gelu1(v0.y);
                v1.x = gelu1(v1.x); v1.y = gelu1(v1.y);
            }
            if (OUTH) {
                __half2* C = (__half2*)Cv;
                C[((size_t)row * ldc + col) >> 1]       = __floats2half2_rn(v0.x, v0.y);
                C[((size_t)(row + 8) * ldc + col) >> 1] = __floats2half2_rn(v1.x, v1.y);
            } else {
                float* C = (float*)Cv;
                *(float2*)(C + (size_t)row * ldc + col) = v0;
                *(float2*)(C + (size_t)(row + 8) * ldc + col) = v1;
            }
        }
    }
}

// ---------------- Flash attention (tf32, fp16 output) ----------------
__global__ __launch_bounds__(256)
void flash_kernel(const float* __restrict__ qkv, __half* __restrict__ olin) {
    extern __shared__ float sm[];
    float* Qs = sm;
    float* Ks = Qs + 128 * QK_STRIDE;
    float* Vs = Ks + 128 * QK_STRIDE;
    float* Ps = Vs + 128 * V_STRIDE;

    const int bh = blockIdx.y;
    const int b = bh / HEADS, h = bh % HEADS;
    const int m0 = blockIdx.x * 128;
    const float* Qg = qkv + (size_t)b * SEQ * QKVDIM + h * HD;
    const float* Kg = Qg + DIM;
    const float* Vg = Qg + 2 * DIM;

    const int tid = threadIdx.x, lane = tid & 31, warp = tid >> 5;
    const int gid = lane >> 2, qid = lane & 3;

    #pragma unroll
    for (int i = 0; i < 8; i++) {
        int f = i * 256 + tid;
        int r = f >> 4, c4 = (f & 15) * 4;
        float4 v = *(const float4*)(Qg + (size_t)(m0 + r) * QKVDIM + c4);
        v.x *= 0.125f; v.y *= 0.125f; v.z *= 0.125f; v.w *= 0.125f;
        sts_tf32(&Qs[r * QK_STRIDE + c4], v);
    }
    __syncthreads();

    float qf[8][4];
    #pragma unroll
    for (int kk = 0; kk < 8; kk++) {
        const float* p = &Qs[(warp * 16 + gid) * QK_STRIDE + kk * 8 + qid];
        qf[kk][0] = p[0];
        qf[kk][1] = p[8 * QK_STRIDE];
        qf[kk][2] = p[4];
        qf[kk][3] = p[8 * QK_STRIDE + 4];
    }

    float m_i[2] = {-1e30f, -1e30f};
    float l_i[2] = {0.f, 0.f};
    float oacc[8][4];
    #pragma unroll
    for (int nt = 0; nt < 8; nt++)
        #pragma unroll
        for (int r = 0; r < 4; r++) oacc[nt][r] = 0.f;

    float* Pw = Ps + warp * 16 * P_STRIDE;

    for (int kc = 0; kc < 8; kc++) {
        __syncthreads();
        const float* Kc = Kg + (size_t)(kc * 128) * QKVDIM;
        const float* Vc = Vg + (size_t)(kc * 128) * QKVDIM;
        #pragma unroll
        for (int i = 0; i < 8; i++) {
            int f = i * 256 + tid;
            int r = f >> 4, c4 = (f & 15) * 4;
            float4 kv = *(const float4*)(Kc + (size_t)r * QKVDIM + c4);
            sts_tf32(&Ks[r * QK_STRIDE + c4], kv);
            float4 vv = *(const float4*)(Vc + (size_t)r * QKVDIM + c4);
            sts_tf32(&Vs[r * V_STRIDE + c4], vv);
        }
        __syncthreads();

        float sacc[16][4];
        #pragma unroll
        for (int nt = 0; nt < 16; nt++)
            #pragma unroll
            for (int r = 0; r < 4; r++) sacc[nt][r] = 0.f;
        #pragma unroll
        for (int kk = 0; kk < 8; kk++) {
            #pragma unroll
            for (int nt = 0; nt < 16; nt++) {
                float bf[2];
                const float* p = &Ks[(nt * 8 + gid) * QK_STRIDE + kk * 8 + qid];
                bf[0] = p[0];
                bf[1] = p[4];
                mma8(sacc[nt], qf[kk], bf);
            }
        }

        float mx0 = -1e30f, mx1 = -1e30f;
        #pragma unroll
        for (int nt = 0; nt < 16; nt++) {
            mx0 = fmaxf(mx0, fmaxf(sacc[nt][0], sacc[nt][1]));
            mx1 = fmaxf(mx1, fmaxf(sacc[nt][2], sacc[nt][3]));
        }
        mx0 = fmaxf(mx0, __shfl_xor_sync(0xffffffffu, mx0, 1));
        mx0 = fmaxf(mx0, __shfl_xor_sync(0xffffffffu, mx0, 2));
        mx1 = fmaxf(mx1, __shfl_xor_sync(0xffffffffu, mx1, 1));
        mx1 = fmaxf(mx1, __shfl_xor_sync(0xffffffffu, mx1, 2));

        float mnew0 = fmaxf(m_i[0], mx0);
        float mnew1 = fmaxf(m_i[1], mx1);
        float f0 = __expf(m_i[0] - mnew0);
        float f1 = __expf(m_i[1] - mnew1);
        m_i[0] = mnew0; m_i[1] = mnew1;
        l_i[0] *= f0;   l_i[1] *= f1;
        #pragma unroll
        for (int nt = 0; nt < 8; nt++) {
            oacc[nt][0] *= f0; oacc[nt][1] *= f0;
            oacc[nt][2] *= f1; oacc[nt][3] *= f1;
        }

        float rs0 = 0.f, rs1 = 0.f;
        #pragma unroll
        for (int nt = 0; nt < 16; nt++) {
            float p0 = __expf(sacc[nt][0] - mnew0);
            float p1 = __expf(sacc[nt][1] - mnew0);
            float p2 = __expf(sacc[nt][2] - mnew1);
            float p3 = __expf(sacc[nt][3] - mnew1);
            rs0 += p0 + p1; rs1 += p2 + p3;
            float2 lo; lo.x = tf32f(p0); lo.y = tf32f(p1);
            float2 hi; hi.x = tf32f(p2); hi.y = tf32f(p3);
            *(float2*)&Pw[gid * P_STRIDE + nt * 8 + qid * 2] = lo;
            *(float2*)&Pw[(gid + 8) * P_STRIDE + nt * 8 + qid * 2] = hi;
        }
        rs0 += __shfl_xor_sync(0xffffffffu, rs0, 1);
        rs0 += __shfl_xor_sync(0xffffffffu, rs0, 2);
        rs1 += __shfl_xor_sync(0xffffffffu, rs1, 1);
        rs1 += __shfl_xor_sync(0xffffffffu, rs1, 2);
        l_i[0] += rs0; l_i[1] += rs1;

        __syncwarp();

        #pragma unroll
        for (int kk = 0; kk < 16; kk++) {
            float af[4];
            const float* p = &Pw[gid * P_STRIDE + kk * 8 + qid];
            af[0] = p[0];
            af[1] = p[8 * P_STRIDE];
            af[2] = p[4];
            af[3] = p[8 * P_STRIDE + 4];
            #pragma unroll
            for (int nt = 0; nt < 8; nt++) {
                float bf[2];
                bf[0] = Vs[(kk * 8 + qid) * V_STRIDE + nt * 8 + gid];
                bf[1] = Vs[(kk * 8 + qid + 4) * V_STRIDE + nt * 8 + gid];
                mma8(oacc[nt], af, bf);
            }
        }
        __syncwarp();
    }

    float inv0 = 1.f / l_i[0];
    float inv1 = 1.f / l_i[1];
    __half2* C = (__half2*)(olin + (size_t)b * SEQ * DIM + h * HD);
    int row = m0 + warp * 16 + gid;
    #pragma unroll
    for (int nt = 0; nt < 8; nt++) {
        int col = nt * 8 + qid * 2;
        C[((size_t)row * DIM + col) >> 1] =
            __floats2half2_rn(oacc[nt][0] * inv0, oacc[nt][1] * inv0);
        C[((size_t)(row + 8) * DIM + col) >> 1] =
            __floats2half2_rn(oacc[nt][2] * inv1, oacc[nt][3] * inv1);
    }
}

// ---------------- launch ----------------
extern "C" void kernel_launch(void* const* d_in, const int* in_sizes, int n_in,
                              void* d_out, int out_size) {
    const float* x       = (const float*)d_in[0];
    const float* n1g     = (const float*)d_in[1];
    const float* n1b     = (const float*)d_in[2];
    const float* qkv_w   = (const float*)d_in[3];
    const float* qkv_b   = (const float*)d_in[4];
    const float* proj_w  = (const float*)d_in[5];
    const float* proj_b  = (const float*)d_in[6];
    const float* n2g     = (const float*)d_in[7];
    const float* n2b     = (const float*)d_in[8];
    const float* fc1_w   = (const float*)d_in[9];
    const float* fc1_b   = (const float*)d_in[10];
    const float* fc2_w   = (const float*)d_in[11];
    const float* fc2_b   = (const float*)d_in[12];
    float* out = (float*)d_out;

    __half *h1h, *h2h, *olinh, *h3h, *qkvwh, *projwh, *fc1wh, *fc2wh;
    float *qkv, *x2;
    cudaGetSymbolAddress((void**)&h1h,    g_h1h);
    cudaGetSymbolAddress((void**)&h2h,    g_h2h);
    cudaGetSymbolAddress((void**)&olinh,  g_olinh);
    cudaGetSymbolAddress((void**)&h3h,    g_h3h);
    cudaGetSymbolAddress((void**)&qkv,    g_qkv);
    cudaGetSymbolAddress((void**)&x2,     g_x2);
    cudaGetSymbolAddress((void**)&qkvwh,  g_qkvwh);
    cudaGetSymbolAddress((void**)&projwh, g_projwh);
    cudaGetSymbolAddress((void**)&fc1wh,  g_fc1wh);
    cudaGetSymbolAddress((void**)&fc2wh,  g_fc2wh);

    cudaFuncSetAttribute(hgemm_tn_kernel<EPI_BIAS, 0>,
                         cudaFuncAttributeMaxDynamicSharedMemorySize, GEMM_SMEM);
    cudaFuncSetAttribute(hgemm_tn_kernel<EPI_BIAS_RES, 0>,
                         cudaFuncAttributeMaxDynamicSharedMemorySize, GEMM_SMEM);
    cudaFuncSetAttribute(hgemm_tn_kernel<EPI_BIAS_GELU, 1>,
                         cudaFuncAttributeMaxDynamicSharedMemorySize, GEMM_SMEM);
    cudaFuncSetAttribute(flash_kernel,
                         cudaFuncAttributeMaxDynamicSharedMemorySize, FLASH_SMEM);

    // 0) weight fp32 -> fp16
    cvt_f2h<<<(QKVDIM*DIM/4 + 255)/256, 256>>>((const float4*)qkv_w, (__half2*)qkvwh, QKVDIM*DIM/4);
    cvt_f2h<<<(DIM*DIM/4 + 255)/256, 256>>>((const float4*)proj_w, (__half2*)projwh, DIM*DIM/4);
    cvt_f2h<<<(HIDDEN*DIM/4 + 255)/256, 256>>>((const float4*)fc1_w, (__half2*)fc1wh, HIDDEN*DIM/4);
    cvt_f2h<<<(DIM*HIDDEN/4 + 255)/256, 256>>>((const float4*)fc2_w, (__half2*)fc2wh, DIM*HIDDEN/4);

    // 1) LN1 -> fp16
    ln_kernel<<<TOK, 256>>>(x, n1g, n1b, h1h);
    // 2) QKV = h1 @ qkv_w^T + b  (fp32 out for flash)
    hgemm_tn_kernel<EPI_BIAS, 0><<<dim3(QKVDIM/128, TOK/128), 128, GEMM_SMEM>>>(
        h1h, DIM, qkvwh, DIM, qkv, QKVDIM, DIM, qkv_b, nullptr, 0);
    // 3) fused attention -> olin (fp16)
    flash_kernel<<<dim3(SEQ/128, NBH), 256, FLASH_SMEM>>>(qkv, olinh);
    // 4) x2 = x + olin @ proj_w^T + b (fp32)
    hgemm_tn_kernel<EPI_BIAS_RES, 0><<<dim3(DIM/128, TOK/128), 128, GEMM_SMEM>>>(
        olinh, DIM, projwh, DIM, x2, DIM, DIM, proj_b, x, DIM);
    // 5) LN2 -> fp16
    ln_kernel<<<TOK, 256>>>(x2, n2g, n2b, h2h);
    // 6) h3 = gelu(h2 @ fc1_w^T + b) (fp16 out)
    hgemm_tn_kernel<EPI_BIAS_GELU, 1><<<dim3(HIDDEN/128, TOK/128), 128, GEMM_SMEM>>>(
        h2h, DIM, fc1wh, DIM, h3h, HIDDEN, DIM, fc1_b, nullptr, 0);
    // 7) out = x2 + h3 @ fc2_w^T + b (fp32)
    hgemm_tn_kernel<EPI_BIAS_RES, 0><<<dim3(DIM/128, TOK/128), 128, GEMM_SMEM>>>(
        h3h, HIDDEN, fc2wh, HIDDEN, out, DIM, HIDDEN, fc2_b, x2, DIM);
}

// round 9
// speedup vs baseline: 1.8308x; 1.2139x over previous
#include <cuda_runtime.h>
#include <cuda_fp16.h>
#include <math.h>
#include <stdint.h>

// Problem dims
#define DIM     768
#define HEADS   12
#define HD      64
#define HIDDEN  3072
#define SEQ     1024
#define BATCHN  8
#define TOK     (BATCHN*SEQ)   // 8192
#define QKVDIM  (3*DIM)        // 2304
#define NBH     (BATCHN*HEADS) // 96

// fp16 GEMM tiling
#define BKH      64
#define HSTRIDE  72
#define STAGE_H  (128 * HSTRIDE)
#define GEMM_SMEM (2 * 2 * STAGE_H * 2)    // 73728 B

// fp16 flash smem (halves)
#define FQ_STRIDE 72                        // 64 + 8 pad
#define FP_STRIDE 136                       // 128 + 8 pad
#define FLASH_SMEM ((3*128*FQ_STRIDE + 8*16*FP_STRIDE) * 2)   // 90112 B

// ---------------- scratch ----------------
__device__ __half g_h1h[TOK*DIM];
__device__ __half g_h2h[TOK*DIM];
__device__ __half g_olinh[TOK*DIM];
__device__ __half g_h3h[(size_t)TOK*HIDDEN];
__device__ __half g_qkvh[(size_t)TOK*QKVDIM];
__device__ float  g_x2[TOK*DIM];
__device__ __half g_qkvwh[QKVDIM*DIM];
__device__ __half g_projwh[DIM*DIM];
__device__ __half g_fc1wh[HIDDEN*DIM];
__device__ __half g_fc2wh[DIM*HIDDEN];

// ---------------- helpers ----------------
__device__ __forceinline__ void mma16(float* d, const uint32_t* a, uint32_t b0, uint32_t b1) {
    asm volatile(
        "mma.sync.aligned.m16n8k16.row.col.f32.f16.f16.f32 "
        "{%0,%1,%2,%3}, {%4,%5,%6,%7}, {%8,%9}, {%0,%1,%2,%3};"
        : "+f"(d[0]), "+f"(d[1]), "+f"(d[2]), "+f"(d[3])
        : "r"(a[0]), "r"(a[1]), "r"(a[2]), "r"(a[3]), "r"(b0), "r"(b1));
}
__device__ __forceinline__ float gelu1(float x) {
    return 0.5f * x * (1.f + erff(x * 0.70710678118654752f));
}
__device__ __forceinline__ void cp16h(__half* dst, const __half* src) {
    unsigned d = (unsigned)__cvta_generic_to_shared(dst);
    asm volatile("cp.async.cg.shared.global [%0], [%1], 16;\n" :: "r"(d), "l"(src));
}
__device__ __forceinline__ void cp_commit() {
    asm volatile("cp.async.commit_group;\n");
}
template<int N>
__device__ __forceinline__ void cp_wait() {
    asm volatile("cp.async.wait_group %0;\n" :: "n"(N));
}

// ---------------- fused fp32 -> fp16 converter (all 4 weights) ----------------
__global__ void cvt_all(const float4* __restrict__ s0, __half2* __restrict__ d0, int n0,
                        const float4* __restrict__ s1, __half2* __restrict__ d1, int n1,
                        const float4* __restrict__ s2, __half2* __restrict__ d2, int n2,
                        const float4* __restrict__ s3, __half2* __restrict__ d3, int n3) {
    int i = blockIdx.x * blockDim.x + threadIdx.x;
    const float4* s; __half2* d;
    if (i < n0) { s = s0; d = d0; }
    else if ((i -= n0) < n1) { s = s1; d = d1; }
    else if ((i -= n1) < n2) { s = s2; d = d2; }
    else if ((i -= n2) < n3) { s = s3; d = d3; }
    else return;
    float4 v = s[i];
    d[2*i]   = __floats2half2_rn(v.x, v.y);
    d[2*i+1] = __floats2half2_rn(v.z, v.w);
}

// ---------------- LayerNorm (fp32 in, fp16 out) ----------------
__global__ void ln_kernel(const float* __restrict__ in,
                          const float* __restrict__ gam,
                          const float* __restrict__ bet,
                          __half* __restrict__ out) {
    int row = blockIdx.x;
    int t = threadIdx.x;
    const float* x = in + (size_t)row * DIM;
    float v0 = x[t], v1 = x[t + 256], v2 = x[t + 512];
    float s  = v0 + v1 + v2;
    float sq = v0*v0 + v1*v1 + v2*v2;
    __shared__ float redS[8], redQ[8];
    #pragma unroll
    for (int o = 16; o > 0; o >>= 1) {
        s  += __shfl_xor_sync(0xffffffffu, s,  o);
        sq += __shfl_xor_sync(0xffffffffu, sq, o);
    }
    if ((t & 31) == 0) { redS[t >> 5] = s; redQ[t >> 5] = sq; }
    __syncthreads();
    if (t < 32) {
        float s2 = (t < 8) ? redS[t] : 0.f;
        float q2 = (t < 8) ? redQ[t] : 0.f;
        #pragma unroll
        for (int o = 4; o > 0; o >>= 1) {
            s2 += __shfl_xor_sync(0xffffffffu, s2, o);
            q2 += __shfl_xor_sync(0xffffffffu, q2, o);
        }
        if (t == 0) { redS[0] = s2; redQ[0] = q2; }
    }
    __syncthreads();
    float mu  = redS[0] * (1.0f / DIM);
    float var = redQ[0] * (1.0f / DIM) - mu * mu;
    float inv = rsqrtf(var + 1e-5f);
    __half* o = out + (size_t)row * DIM;
    o[t]       = __float2half((v0 - mu) * inv * gam[t]       + bet[t]);
    o[t + 256] = __float2half((v1 - mu) * inv * gam[t + 256] + bet[t + 256]);
    o[t + 512] = __float2half((v2 - mu) * inv * gam[t + 512] + bet[t + 512]);
}

// ---------------- FP16 MMA GEMM (TN) — unchanged from R8 ----------------
enum { EPI_BIAS = 1, EPI_BIAS_RES = 2, EPI_BIAS_GELU = 3 };

template<int EPI, int OUTH>
__global__ __launch_bounds__(128)
void hgemm_tn_kernel(const __half* __restrict__ A, int lda,
                     const __half* __restrict__ W, int ldw,
                     void* __restrict__ Cv, int ldc, int K,
                     const float* __restrict__ bias,
                     const float* __restrict__ res, int ldres) {
    extern __shared__ __half smh[];
    const int m0 = blockIdx.y * 128, n0 = blockIdx.x * 128;
    const int tid  = threadIdx.x;
    const int lane = tid & 31;
    const int warp = tid >> 5;
    const int m0w  = (warp >> 1) * 64;
    const int n0w  = (warp & 1) * 64;
    const int gid  = lane >> 2;
    const int qid  = lane & 3;

    const int crow0 = tid >> 3;
    const int cgr   = tid & 7;

    float acc[4][8][4];
    #pragma unroll
    for (int i = 0; i < 4; i++)
        #pragma unroll
        for (int j = 0; j < 8; j++)
            #pragma unroll
            for (int r = 0; r < 4; r++) acc[i][j][r] = 0.f;

    const int nch = K / BKH;

    auto load_chunk = [&](int j) {
        __half* as = smh + (j & 1) * 2 * STAGE_H;
        __half* ws = as + STAGE_H;
        const __half* Aj = A + (size_t)m0 * lda + j * BKH + cgr * 8;
        const __half* Wj = W + (size_t)n0 * ldw + j * BKH + cgr * 8;
        #pragma unroll
        for (int r = 0; r < 8; r++) {
            int row = crow0 + r * 16;
            cp16h(&as[row * HSTRIDE + cgr * 8], Aj + (size_t)row * lda);
            cp16h(&ws[row * HSTRIDE + cgr * 8], Wj + (size_t)row * ldw);
        }
    };

    load_chunk(0);
    cp_commit();

    for (int i = 0; i < nch; i++) {
        cp_wait<0>();
        __syncthreads();

        if (i + 1 < nch) {
            load_chunk(i + 1);
            cp_commit();
        }

        const __half* As = smh + (i & 1) * 2 * STAGE_H;
        const __half* Ws = As + STAGE_H;
        #pragma unroll
        for (int ks = 0; ks < 4; ks++) {
            const int w0 = ks * 8 + qid;
            uint32_t af[4][4];
            #pragma unroll
            for (int mt = 0; mt < 4; mt++) {
                const uint32_t* p0 = (const uint32_t*)(As + (m0w + mt * 16 + gid) * HSTRIDE);
                const uint32_t* p1 = (const uint32_t*)(As + (m0w + mt * 16 + gid + 8) * HSTRIDE);
                af[mt][0] = p0[w0];
                af[mt][1] = p1[w0];
                af[mt][2] = p0[w0 + 4];
                af[mt][3] = p1[w0 + 4];
            }
            #pragma unroll
            for (int nt = 0; nt < 8; nt++) {
                const uint32_t* pb = (const uint32_t*)(Ws + (n0w + nt * 8 + gid) * HSTRIDE);
                uint32_t b0 = pb[w0];
                uint32_t b1 = pb[w0 + 4];
                #pragma unroll
                for (int mt = 0; mt < 4; mt++)
                    mma16(acc[mt][nt], af[mt], b0, b1);
            }
        }
    }

    #pragma unroll
    for (int mt = 0; mt < 4; mt++) {
        #pragma unroll
        for (int nt = 0; nt < 8; nt++) {
            int row = m0 + m0w + mt * 16 + gid;
            int col = n0 + n0w + nt * 8 + qid * 2;
            float2 v0, v1;
            v0.x = acc[mt][nt][0]; v0.y = acc[mt][nt][1];
            v1.x = acc[mt][nt][2]; v1.y = acc[mt][nt][3];
            {
                float2 bb = *(const float2*)(bias + col);
                v0.x += bb.x; v0.y += bb.y; v1.x += bb.x; v1.y += bb.y;
            }
            if (EPI == EPI_BIAS_RES) {
                float2 r0 = *(const float2*)(res + (size_t)row * ldres + col);
                float2 r1 = *(const float2*)(res + (size_t)(row + 8) * ldres + col);
                v0.x += r0.x; v0.y += r0.y; v1.x += r1.x; v1.y += r1.y;
            }
            if (EPI == EPI_BIAS_GELU) {
                v0.x = gelu1(v0.x); v0.y = gelu1(v0.y);
                v1.x = gelu1(v1.x); v1.y = gelu1(v1.y);
            }
            if (OUTH) {
                __half2* C = (__half2*)Cv;
                C[((size_t)row * ldc + col) >> 1]       = __floats2half2_rn(v0.x, v0.y);
                C[((size_t)(row + 8) * ldc + col) >> 1] = __floats2half2_rn(v1.x, v1.y);
            } else {
                float* C = (float*)Cv;
                *(float2*)(C + (size_t)row * ldc + col) = v0;
                *(float2*)(C + (size_t)(row + 8) * ldc + col) = v1;
            }
        }
    }
}

// ---------------- FP16 flash attention ----------------
// Grid (SEQ/128, NBH), 256 thr (8 warps x 16 q-rows).
// Q/K/V fp16 via cp.async; QK: m16n8k16 word-load B; PV: ldmatrix.x4.trans for V.
__global__ __launch_bounds__(256)
void flash_kernel(const __half* __restrict__ qkv, __half* __restrict__ olin) {
    extern __shared__ __half smf[];
    __half* Qs = smf;
    __half* Ks = Qs + 128 * FQ_STRIDE;
    __half* Vs = Ks + 128 * FQ_STRIDE;
    __half* Ps = Vs + 128 * FQ_STRIDE;

    const int bh = blockIdx.y;
    const int b = bh / HEADS, h = bh % HEADS;
    const int m0 = blockIdx.x * 128;
    const __half* Qg = qkv + (size_t)b * SEQ * QKVDIM + h * HD;
    const __half* Kg = Qg + DIM;
    const __half* Vg = Qg + 2 * DIM;

    const int tid = threadIdx.x, lane = tid & 31, warp = tid >> 5;
    const int gid = lane >> 2, qid = lane & 3;

    // Q tile: 128 x 64 halves, 1024 16B chunks, 4 per thread
    #pragma unroll
    for (int i = 0; i < 4; i++) {
        int f = i * 256 + tid;
        int r = f >> 3, c8 = (f & 7) * 8;
        cp16h(&Qs[r * FQ_STRIDE + c8], Qg + (size_t)(m0 + r) * QKVDIM + c8);
    }
    cp_commit();
    cp_wait<0>();
    __syncthreads();

    // preload Q fragments (4 k-steps of 16)
    uint32_t qf[4][4];
    {
        const uint32_t* q0 = (const uint32_t*)(Qs + (warp * 16 + gid) * FQ_STRIDE);
        const uint32_t* q1 = (const uint32_t*)(Qs + (warp * 16 + gid + 8) * FQ_STRIDE);
        #pragma unroll
        for (int kk = 0; kk < 4; kk++) {
            int w0 = kk * 8 + qid;
            qf[kk][0] = q0[w0];
            qf[kk][1] = q1[w0];
            qf[kk][2] = q0[w0 + 4];
            qf[kk][3] = q1[w0 + 4];
        }
    }

    float m_i[2] = {-1e30f, -1e30f};
    float l_i[2] = {0.f, 0.f};
    float oacc[8][4];
    #pragma unroll
    for (int nt = 0; nt < 8; nt++)
        #pragma unroll
        for (int r = 0; r < 4; r++) oacc[nt][r] = 0.f;

    __half* Pw = Ps + warp * 16 * FP_STRIDE;
    const uint32_t vbase = (uint32_t)__cvta_generic_to_shared(Vs);
    const int t4 = lane >> 3, r8 = lane & 7;   // ldmatrix address lanes

    for (int kc = 0; kc < 8; kc++) {
        __syncthreads();   // prev chunk K/V reads done
        const __half* Kc = Kg + (size_t)(kc * 128) * QKVDIM;
        const __half* Vc = Vg + (size_t)(kc * 128) * QKVDIM;
        #pragma unroll
        for (int i = 0; i < 4; i++) {
            int f = i * 256 + tid;
            int r = f >> 3, c8 = (f & 7) * 8;
            cp16h(&Ks[r * FQ_STRIDE + c8], Kc + (size_t)r * QKVDIM + c8);
            cp16h(&Vs[r * FQ_STRIDE + c8], Vc + (size_t)r * QKVDIM + c8);
        }
        cp_commit();
        cp_wait<0>();
        __syncthreads();

        // S = Q K^T * 0.125
        float sacc[16][4];
        #pragma unroll
        for (int nt = 0; nt < 16; nt++)
            #pragma unroll
            for (int r = 0; r < 4; r++) sacc[nt][r] = 0.f;
        #pragma unroll
        for (int kk = 0; kk < 4; kk++) {
            const int w0 = kk * 8 + qid;
            #pragma unroll
            for (int nt = 0; nt < 16; nt++) {
                const uint32_t* pb = (const uint32_t*)(Ks + (nt * 8 + gid) * FQ_STRIDE);
                mma16(sacc[nt], qf[kk], pb[w0], pb[w0 + 4]);
            }
        }
        #pragma unroll
        for (int nt = 0; nt < 16; nt++) {
            sacc[nt][0] *= 0.125f; sacc[nt][1] *= 0.125f;
            sacc[nt][2] *= 0.125f; sacc[nt][3] *= 0.125f;
        }

        // row max
        float mx0 = -1e30f, mx1 = -1e30f;
        #pragma unroll
        for (int nt = 0; nt < 16; nt++) {
            mx0 = fmaxf(mx0, fmaxf(sacc[nt][0], sacc[nt][1]));
            mx1 = fmaxf(mx1, fmaxf(sacc[nt][2], sacc[nt][3]));
        }
        mx0 = fmaxf(mx0, __shfl_xor_sync(0xffffffffu, mx0, 1));
        mx0 = fmaxf(mx0, __shfl_xor_sync(0xffffffffu, mx0, 2));
        mx1 = fmaxf(mx1, __shfl_xor_sync(0xffffffffu, mx1, 1));
        mx1 = fmaxf(mx1, __shfl_xor_sync(0xffffffffu, mx1, 2));

        float mnew0 = fmaxf(m_i[0], mx0);
        float mnew1 = fmaxf(m_i[1], mx1);
        float f0 = __expf(m_i[0] - mnew0);
        float f1 = __expf(m_i[1] - mnew1);
        m_i[0] = mnew0; m_i[1] = mnew1;
        l_i[0] *= f0;   l_i[1] *= f1;
        #pragma unroll
        for (int nt = 0; nt < 8; nt++) {
            oacc[nt][0] *= f0; oacc[nt][1] *= f0;
            oacc[nt][2] *= f1; oacc[nt][3] *= f1;
        }

        // P = exp(S - m) -> fp16 smem; row sums
        float rs0 = 0.f, rs1 = 0.f;
        #pragma unroll
        for (int nt = 0; nt < 16; nt++) {
            float p0 = __expf(sacc[nt][0] - mnew0);
            float p1 = __expf(sacc[nt][1] - mnew0);
            float p2 = __expf(sacc[nt][2] - mnew1);
            float p3 = __expf(sacc[nt][3] - mnew1);
            rs0 += p0 + p1; rs1 += p2 + p3;
            *(__half2*)&Pw[gid * FP_STRIDE + nt * 8 + qid * 2] = __floats2half2_rn(p0, p1);
            *(__half2*)&Pw[(gid + 8) * FP_STRIDE + nt * 8 + qid * 2] = __floats2half2_rn(p2, p3);
        }
        rs0 += __shfl_xor_sync(0xffffffffu, rs0, 1);
        rs0 += __shfl_xor_sync(0xffffffffu, rs0, 2);
        rs1 += __shfl_xor_sync(0xffffffffu, rs1, 1);
        rs1 += __shfl_xor_sync(0xffffffffu, rs1, 2);
        l_i[0] += rs0; l_i[1] += rs1;

        __syncwarp();

        // O += P @ V : 8 k-steps of 16; V via ldmatrix.x4.trans
        #pragma unroll
        for (int kk2 = 0; kk2 < 8; kk2++) {
            uint32_t ap[4];
            const uint32_t* p0 = (const uint32_t*)(Pw + gid * FP_STRIDE);
            const uint32_t* p1 = (const uint32_t*)(Pw + (gid + 8) * FP_STRIDE);
            int w0 = kk2 * 8 + qid;
            ap[0] = p0[w0]; ap[1] = p1[w0]; ap[2] = p0[w0 + 4]; ap[3] = p1[w0 + 4];
            #pragma unroll
            for (int ntp = 0; ntp < 4; ntp++) {
                int vrow = kk2 * 16 + (t4 & 1) * 8 + r8;
                int vcol = ntp * 16 + (t4 >> 1) * 8;
                uint32_t addr = vbase + (uint32_t)(vrow * FQ_STRIDE + vcol) * 2u;
                uint32_t r0, r1, r2, r3;
                asm volatile(
                    "ldmatrix.sync.aligned.m8n8.x4.trans.shared.b16 {%0,%1,%2,%3}, [%4];"
                    : "=r"(r0), "=r"(r1), "=r"(r2), "=r"(r3) : "r"(addr));
                mma16(oacc[2 * ntp],     ap, r0, r1);
                mma16(oacc[2 * ntp + 1], ap, r2, r3);
            }
        }
        __syncwarp();
    }

    float inv0 = 1.f / l_i[0];
    float inv1 = 1.f / l_i[1];
    __half2* C = (__half2*)(olin + (size_t)b * SEQ * DIM + h * HD);
    int row = m0 + warp * 16 + gid;
    #pragma unroll
    for (int nt = 0; nt < 8; nt++) {
        int col = nt * 8 + qid * 2;
        C[((size_t)row * DIM + col) >> 1] =
            __floats2half2_rn(oacc[nt][0] * inv0, oacc[nt][1] * inv0);
        C[((size_t)(row + 8) * DIM + col) >> 1] =
            __floats2half2_rn(oacc[nt][2] * inv1, oacc[nt][3] * inv1);
    }
}

// ---------------- launch ----------------
extern "C" void kernel_launch(void* const* d_in, const int* in_sizes, int n_in,
                              void* d_out, int out_size) {
    const float* x       = (const float*)d_in[0];
    const float* n1g     = (const float*)d_in[1];
    const float* n1b     = (const float*)d_in[2];
    const float* qkv_w   = (const float*)d_in[3];
    const float* qkv_b   = (const float*)d_in[4];
    const float* proj_w  = (const float*)d_in[5];
    const float* proj_b  = (const float*)d_in[6];
    const float* n2g     = (const float*)d_in[7];
    const float* n2b     = (const float*)d_in[8];
    const float* fc1_w   = (const float*)d_in[9];
    const float* fc1_b   = (const float*)d_in[10];
    const float* fc2_w   = (const float*)d_in[11];
    const float* fc2_b   = (const float*)d_in[12];
    float* out = (float*)d_out;

    __half *h1h, *h2h, *olinh, *h3h, *qkvh, *qkvwh, *projwh, *fc1wh, *fc2wh;
    float *x2;
    cudaGetSymbolAddress((void**)&h1h,    g_h1h);
    cudaGetSymbolAddress((void**)&h2h,    g_h2h);
    cudaGetSymbolAddress((void**)&olinh,  g_olinh);
    cudaGetSymbolAddress((void**)&h3h,    g_h3h);
    cudaGetSymbolAddress((void**)&qkvh,   g_qkvh);
    cudaGetSymbolAddress((void**)&x2,     g_x2);
    cudaGetSymbolAddress((void**)&qkvwh,  g_qkvwh);
    cudaGetSymbolAddress((void**)&projwh, g_projwh);
    cudaGetSymbolAddress((void**)&fc1wh,  g_fc1wh);
    cudaGetSymbolAddress((void**)&fc2wh,  g_fc2wh);

    cudaFuncSetAttribute(hgemm_tn_kernel<EPI_BIAS, 1>,
                         cudaFuncAttributeMaxDynamicSharedMemorySize, GEMM_SMEM);
    cudaFuncSetAttribute(hgemm_tn_kernel<EPI_BIAS_RES, 0>,
                         cudaFuncAttributeMaxDynamicSharedMemorySize, GEMM_SMEM);
    cudaFuncSetAttribute(hgemm_tn_kernel<EPI_BIAS_GELU, 1>,
                         cudaFuncAttributeMaxDynamicSharedMemorySize, GEMM_SMEM);
    cudaFuncSetAttribute(flash_kernel,
                         cudaFuncAttributeMaxDynamicSharedMemorySize, FLASH_SMEM);

    // 0) all weights fp32 -> fp16, one launch
    const int n0 = QKVDIM*DIM/4, n1 = DIM*DIM/4, n2 = HIDDEN*DIM/4, n3 = DIM*HIDDEN/4;
    cvt_all<<<(n0+n1+n2+n3 + 255)/256, 256>>>(
        (const float4*)qkv_w,  (__half2*)qkvwh,  n0,
        (const float4*)proj_w, (__half2*)projwh, n1,
        (const float4*)fc1_w,  (__half2*)fc1wh,  n2,
        (const float4*)fc2_w,  (__half2*)fc2wh,  n3);

    // 1) LN1 -> fp16
    ln_kernel<<<TOK, 256>>>(x, n1g, n1b, h1h);
    // 2) QKV = h1 @ qkv_w^T + b  (fp16 out)
    hgemm_tn_kernel<EPI_BIAS, 1><<<dim3(QKVDIM/128, TOK/128), 128, GEMM_SMEM>>>(
        h1h, DIM, qkvwh, DIM, qkvh, QKVDIM, DIM, qkv_b, nullptr, 0);
    // 3) fused fp16 attention -> olin (fp16)
    flash_kernel<<<dim3(SEQ/128, NBH), 256, FLASH_SMEM>>>(qkvh, olinh);
    // 4) x2 = x + olin @ proj_w^T + b (fp32)
    hgemm_tn_kernel<EPI_BIAS_RES, 0><<<dim3(DIM/128, TOK/128), 128, GEMM_SMEM>>>(
        olinh, DIM, projwh, DIM, x2, DIM, DIM, proj_b, x, DIM);
    // 5) LN2 -> fp16
    ln_kernel<<<TOK, 256>>>(x2, n2g, n2b, h2h);
    // 6) h3 = gelu(h2 @ fc1_w^T + b) (fp16 out)
    hgemm_tn_kernel<EPI_BIAS_GELU, 1><<<dim3(HIDDEN/128, TOK/128), 128, GEMM_SMEM>>>(
        h2h, DIM, fc1wh, DIM, h3h, HIDDEN, DIM, fc1_b, nullptr, 0);
    // 7) out = x2 + h3 @ fc2_w^T + b (fp32)
    hgemm_tn_kernel<EPI_BIAS_RES, 0><<<dim3(DIM/128, TOK/128), 128, GEMM_SMEM>>>(
        h3h, HIDDEN, fc2wh, HIDDEN, out, DIM, HIDDEN, fc2_b, x2, DIM);
}

// round 10
// speedup vs baseline: 1.8370x; 1.0034x over previous
#include <cuda_runtime.h>
#include <cuda_fp16.h>
#include <math.h>
#include <stdint.h>

// Problem dims
#define DIM     768
#define HEADS   12
#define HD      64
#define HIDDEN  3072
#define SEQ     1024
#define BATCHN  8
#define TOK     (BATCHN*SEQ)   // 8192
#define QKVDIM  (3*DIM)        // 2304
#define NBH     (BATCHN*HEADS) // 96

// fp16 GEMM tiling
#define BKH      64
#define HSTRIDE  72
#define STAGE_H  (128 * HSTRIDE)
#define GEMM_SMEM (2 * 2 * STAGE_H * 2)    // 73728 B

// fp16 flash smem (halves); layout: Q | K0 | V0 | K1 | V1 | P
#define FQ_STRIDE 72
#define FP_STRIDE 136
#define FTILE_H   (128 * FQ_STRIDE)                 // 9216 halves per tile
#define FLASH_SMEM ((5 * FTILE_H + 8 * 16 * FP_STRIDE) * 2)   // 126976 B

// ---------------- scratch ----------------
__device__ __half g_h1h[TOK*DIM];
__device__ __half g_h2h[TOK*DIM];
__device__ __half g_olinh[TOK*DIM];
__device__ __half g_h3h[(size_t)TOK*HIDDEN];
__device__ __half g_qkvh[(size_t)TOK*QKVDIM];
__device__ float  g_x2[TOK*DIM];
__device__ __half g_qkvwh[QKVDIM*DIM];
__device__ __half g_projwh[DIM*DIM];
__device__ __half g_fc1wh[HIDDEN*DIM];
__device__ __half g_fc2wh[DIM*HIDDEN];

// ---------------- helpers ----------------
__device__ __forceinline__ void mma16(float* d, const uint32_t* a, uint32_t b0, uint32_t b1) {
    asm volatile(
        "mma.sync.aligned.m16n8k16.row.col.f32.f16.f16.f32 "
        "{%0,%1,%2,%3}, {%4,%5,%6,%7}, {%8,%9}, {%0,%1,%2,%3};"
        : "+f"(d[0]), "+f"(d[1]), "+f"(d[2]), "+f"(d[3])
        : "r"(a[0]), "r"(a[1]), "r"(a[2]), "r"(a[3]), "r"(b0), "r"(b1));
}
__device__ __forceinline__ float gelu1(float x) {
    return 0.5f * x * (1.f + erff(x * 0.70710678118654752f));
}
__device__ __forceinline__ void cp16h(__half* dst, const __half* src) {
    unsigned d = (unsigned)__cvta_generic_to_shared(dst);
    asm volatile("cp.async.cg.shared.global [%0], [%1], 16;\n" :: "r"(d), "l"(src));
}
__device__ __forceinline__ void cp_commit() {
    asm volatile("cp.async.commit_group;\n");
}
template<int N>
__device__ __forceinline__ void cp_wait() {
    asm volatile("cp.async.wait_group %0;\n" :: "n"(N));
}

// ---------------- fused fp32 -> fp16 converter (all 4 weights) ----------------
__global__ void cvt_all(const float4* __restrict__ s0, __half2* __restrict__ d0, int n0,
                        const float4* __restrict__ s1, __half2* __restrict__ d1, int n1,
                        const float4* __restrict__ s2, __half2* __restrict__ d2, int n2,
                        const float4* __restrict__ s3, __half2* __restrict__ d3, int n3) {
    int i = blockIdx.x * blockDim.x + threadIdx.x;
    const float4* s; __half2* d;
    if (i < n0) { s = s0; d = d0; }
    else if ((i -= n0) < n1) { s = s1; d = d1; }
    else if ((i -= n1) < n2) { s = s2; d = d2; }
    else if ((i -= n2) < n3) { s = s3; d = d3; }
    else return;
    float4 v = s[i];
    d[2*i]   = __floats2half2_rn(v.x, v.y);
    d[2*i+1] = __floats2half2_rn(v.z, v.w);
}

// ---------------- LayerNorm (fp32 in, fp16 out) ----------------
__global__ void ln_kernel(const float* __restrict__ in,
                          const float* __restrict__ gam,
                          const float* __restrict__ bet,
                          __half* __restrict__ out) {
    int row = blockIdx.x;
    int t = threadIdx.x;
    const float* x = in + (size_t)row * DIM;
    float v0 = x[t], v1 = x[t + 256], v2 = x[t + 512];
    float s  = v0 + v1 + v2;
    float sq = v0*v0 + v1*v1 + v2*v2;
    __shared__ float redS[8], redQ[8];
    #pragma unroll
    for (int o = 16; o > 0; o >>= 1) {
        s  += __shfl_xor_sync(0xffffffffu, s,  o);
        sq += __shfl_xor_sync(0xffffffffu, sq, o);
    }
    if ((t & 31) == 0) { redS[t >> 5] = s; redQ[t >> 5] = sq; }
    __syncthreads();
    if (t < 32) {
        float s2 = (t < 8) ? redS[t] : 0.f;
        float q2 = (t < 8) ? redQ[t] : 0.f;
        #pragma unroll
        for (int o = 4; o > 0; o >>= 1) {
            s2 += __shfl_xor_sync(0xffffffffu, s2, o);
            q2 += __shfl_xor_sync(0xffffffffu, q2, o);
        }
        if (t == 0) { redS[0] = s2; redQ[0] = q2; }
    }
    __syncthreads();
    float mu  = redS[0] * (1.0f / DIM);
    float var = redQ[0] * (1.0f / DIM) - mu * mu;
    float inv = rsqrtf(var + 1e-5f);
    __half* o = out + (size_t)row * DIM;
    o[t]       = __float2half((v0 - mu) * inv * gam[t]       + bet[t]);
    o[t + 256] = __float2half((v1 - mu) * inv * gam[t + 256] + bet[t + 256]);
    o[t + 512] = __float2half((v2 - mu) * inv * gam[t + 512] + bet[t + 512]);
}

// ---------------- FP16 MMA GEMM (TN) — unchanged from R9 ----------------
enum { EPI_BIAS = 1, EPI_BIAS_RES = 2, EPI_BIAS_GELU = 3 };

template<int EPI, int OUTH>
__global__ __launch_bounds__(128)
void hgemm_tn_kernel(const __half* __restrict__ A, int lda,
                     const __half* __restrict__ W, int ldw,
                     void* __restrict__ Cv, int ldc, int K,
                     const float* __restrict__ bias,
                     const float* __restrict__ res, int ldres) {
    extern __shared__ __half smh[];
    const int m0 = blockIdx.y * 128, n0 = blockIdx.x * 128;
    const int tid  = threadIdx.x;
    const int lane = tid & 31;
    const int warp = tid >> 5;
    const int m0w  = (warp >> 1) * 64;
    const int n0w  = (warp & 1) * 64;
    const int gid  = lane >> 2;
    const int qid  = lane & 3;

    const int crow0 = tid >> 3;
    const int cgr   = tid & 7;

    float acc[4][8][4];
    #pragma unroll
    for (int i = 0; i < 4; i++)
        #pragma unroll
        for (int j = 0; j < 8; j++)
            #pragma unroll
            for (int r = 0; r < 4; r++) acc[i][j][r] = 0.f;

    const int nch = K / BKH;

    auto load_chunk = [&](int j) {
        __half* as = smh + (j & 1) * 2 * STAGE_H;
        __half* ws = as + STAGE_H;
        const __half* Aj = A + (size_t)m0 * lda + j * BKH + cgr * 8;
        const __half* Wj = W + (size_t)n0 * ldw + j * BKH + cgr * 8;
        #pragma unroll
        for (int r = 0; r < 8; r++) {
            int row = crow0 + r * 16;
            cp16h(&as[row * HSTRIDE + cgr * 8], Aj + (size_t)row * lda);
            cp16h(&ws[row * HSTRIDE + cgr * 8], Wj + (size_t)row * ldw);
        }
    };

    load_chunk(0);
    cp_commit();

    for (int i = 0; i < nch; i++) {
        cp_wait<0>();
        __syncthreads();

        if (i + 1 < nch) {
            load_chunk(i + 1);
            cp_commit();
        }

        const __half* As = smh + (i & 1) * 2 * STAGE_H;
        const __half* Ws = As + STAGE_H;
        #pragma unroll
        for (int ks = 0; ks < 4; ks++) {
            const int w0 = ks * 8 + qid;
            uint32_t af[4][4];
            #pragma unroll
            for (int mt = 0; mt < 4; mt++) {
                const uint32_t* p0 = (const uint32_t*)(As + (m0w + mt * 16 + gid) * HSTRIDE);
                const uint32_t* p1 = (const uint32_t*)(As + (m0w + mt * 16 + gid + 8) * HSTRIDE);
                af[mt][0] = p0[w0];
                af[mt][1] = p1[w0];
                af[mt][2] = p0[w0 + 4];
                af[mt][3] = p1[w0 + 4];
            }
            #pragma unroll
            for (int nt = 0; nt < 8; nt++) {
                const uint32_t* pb = (const uint32_t*)(Ws + (n0w + nt * 8 + gid) * HSTRIDE);
                uint32_t b0 = pb[w0];
                uint32_t b1 = pb[w0 + 4];
                #pragma unroll
                for (int mt = 0; mt < 4; mt++)
                    mma16(acc[mt][nt], af[mt], b0, b1);
            }
        }
    }

    #pragma unroll
    for (int mt = 0; mt < 4; mt++) {
        #pragma unroll
        for (int nt = 0; nt < 8; nt++) {
            int row = m0 + m0w + mt * 16 + gid;
            int col = n0 + n0w + nt * 8 + qid * 2;
            float2 v0, v1;
            v0.x = acc[mt][nt][0]; v0.y = acc[mt][nt][1];
            v1.x = acc[mt][nt][2]; v1.y = acc[mt][nt][3];
            {
                float2 bb = *(const float2*)(bias + col);
                v0.x += bb.x; v0.y += bb.y; v1.x += bb.x; v1.y += bb.y;
            }
            if (EPI == EPI_BIAS_RES) {
                float2 r0 = *(const float2*)(res + (size_t)row * ldres + col);
                float2 r1 = *(const float2*)(res + (size_t)(row + 8) * ldres + col);
                v0.x += r0.x; v0.y += r0.y; v1.x += r1.x; v1.y += r1.y;
            }
            if (EPI == EPI_BIAS_GELU) {
                v0.x = gelu1(v0.x); v0.y = gelu1(v0.y);
                v1.x = gelu1(v1.x); v1.y = gelu1(v1.y);
            }
            if (OUTH) {
                __half2* C = (__half2*)Cv;
                C[((size_t)row * ldc + col) >> 1]       = __floats2half2_rn(v0.x, v0.y);
                C[((size_t)(row + 8) * ldc + col) >> 1] = __floats2half2_rn(v1.x, v1.y);
            } else {
                float* C = (float*)Cv;
                *(float2*)(C + (size_t)row * ldc + col) = v0;
                *(float2*)(C + (size_t)(row + 8) * ldc + col) = v1;
            }
        }
    }
}

// ---------------- FP16 flash attention, double-buffered K/V ----------------
__global__ __launch_bounds__(256)
void flash_kernel(const __half* __restrict__ qkv, __half* __restrict__ olin) {
    extern __shared__ __half smf[];
    __half* Qs  = smf;
    __half* KV0 = Qs + FTILE_H;              // K0 at +0, V0 at +FTILE_H
    __half* KV1 = KV0 + 2 * FTILE_H;
    __half* Ps  = KV1 + 2 * FTILE_H;

    const int bh = blockIdx.y;
    const int b = bh / HEADS, h = bh % HEADS;
    const int m0 = blockIdx.x * 128;
    const __half* Qg = qkv + (size_t)b * SEQ * QKVDIM + h * HD;
    const __half* Kg = Qg + DIM;
    const __half* Vg = Qg + 2 * DIM;

    const int tid = threadIdx.x, lane = tid & 31, warp = tid >> 5;
    const int gid = lane >> 2, qid = lane & 3;

    auto load_kv = [&](int kc, __half* dst) {
        const __half* Kc = Kg + (size_t)(kc * 128) * QKVDIM;
        const __half* Vc = Vg + (size_t)(kc * 128) * QKVDIM;
        #pragma unroll
        for (int i = 0; i < 4; i++) {
            int f = i * 256 + tid;
            int r = f >> 3, c8 = (f & 7) * 8;
            cp16h(&dst[r * FQ_STRIDE + c8], Kc + (size_t)r * QKVDIM + c8);
            cp16h(&dst[FTILE_H + r * FQ_STRIDE + c8], Vc + (size_t)r * QKVDIM + c8);
        }
    };

    // group 0: Q tile
    #pragma unroll
    for (int i = 0; i < 4; i++) {
        int f = i * 256 + tid;
        int r = f >> 3, c8 = (f & 7) * 8;
        cp16h(&Qs[r * FQ_STRIDE + c8], Qg + (size_t)(m0 + r) * QKVDIM + c8);
    }
    cp_commit();
    // group 1: KV chunk 0
    load_kv(0, KV0);
    cp_commit();

    cp_wait<1>();          // Q landed (KV0 may still be in flight)
    __syncthreads();

    // preload Q fragments, pre-scaled by 1/8
    const __half2 kscale = __floats2half2_rn(0.125f, 0.125f);
    uint32_t qf[4][4];
    {
        const uint32_t* q0 = (const uint32_t*)(Qs + (warp * 16 + gid) * FQ_STRIDE);
        const uint32_t* q1 = (const uint32_t*)(Qs + (warp * 16 + gid + 8) * FQ_STRIDE);
        #pragma unroll
        for (int kk = 0; kk < 4; kk++) {
            int w0 = kk * 8 + qid;
            uint32_t w;
            w = q0[w0];     { __half2 t = __hmul2(*(__half2*)&w, kscale); qf[kk][0] = *(uint32_t*)&t; }
            w = q1[w0];     { __half2 t = __hmul2(*(__half2*)&w, kscale); qf[kk][1] = *(uint32_t*)&t; }
            w = q0[w0 + 4]; { __half2 t = __hmul2(*(__half2*)&w, kscale); qf[kk][2] = *(uint32_t*)&t; }
            w = q1[w0 + 4]; { __half2 t = __hmul2(*(__half2*)&w, kscale); qf[kk][3] = *(uint32_t*)&t; }
        }
    }

    float m_i[2] = {-1e30f, -1e30f};
    float l_i[2] = {0.f, 0.f};
    float oacc[8][4];
    #pragma unroll
    for (int nt = 0; nt < 8; nt++)
        #pragma unroll
        for (int r = 0; r < 4; r++) oacc[nt][r] = 0.f;

    __half* Pw = Ps + warp * 16 * FP_STRIDE;
    const int t4 = lane >> 3, r8 = lane & 7;

    for (int kc = 0; kc < 8; kc++) {
        __half* cur = (kc & 1) ? KV1 : KV0;
        __half* nxt = (kc & 1) ? KV0 : KV1;

        // prefetch next chunk into the buffer everyone has finished reading
        // (synced at end of previous iteration / prologue)
        if (kc + 1 < 8) load_kv(kc + 1, nxt);
        cp_commit();
        cp_wait<1>();      // current chunk (kc) landed; kc+1 still in flight
        __syncthreads();

        const __half* Ks = cur;
        const uint32_t vbase = (uint32_t)__cvta_generic_to_shared(cur + FTILE_H);

        // S = (Q/8) K^T
        float sacc[16][4];
        #pragma unroll
        for (int nt = 0; nt < 16; nt++)
            #pragma unroll
            for (int r = 0; r < 4; r++) sacc[nt][r] = 0.f;
        #pragma unroll
        for (int kk = 0; kk < 4; kk++) {
            const int w0 = kk * 8 + qid;
            #pragma unroll
            for (int nt = 0; nt < 16; nt++) {
                const uint32_t* pb = (const uint32_t*)(Ks + (nt * 8 + gid) * FQ_STRIDE);
                mma16(sacc[nt], qf[kk], pb[w0], pb[w0 + 4]);
            }
        }

        // row max
        float mx0 = -1e30f, mx1 = -1e30f;
        #pragma unroll
        for (int nt = 0; nt < 16; nt++) {
            mx0 = fmaxf(mx0, fmaxf(sacc[nt][0], sacc[nt][1]));
            mx1 = fmaxf(mx1, fmaxf(sacc[nt][2], sacc[nt][3]));
        }
        mx0 = fmaxf(mx0, __shfl_xor_sync(0xffffffffu, mx0, 1));
        mx0 = fmaxf(mx0, __shfl_xor_sync(0xffffffffu, mx0, 2));
        mx1 = fmaxf(mx1, __shfl_xor_sync(0xffffffffu, mx1, 1));
        mx1 = fmaxf(mx1, __shfl_xor_sync(0xffffffffu, mx1, 2));

        float mnew0 = fmaxf(m_i[0], mx0);
        float mnew1 = fmaxf(m_i[1], mx1);
        float f0 = __expf(m_i[0] - mnew0);
        float f1 = __expf(m_i[1] - mnew1);
        m_i[0] = mnew0; m_i[1] = mnew1;
        l_i[0] *= f0;   l_i[1] *= f1;
        #pragma unroll
        for (int nt = 0; nt < 8; nt++) {
            oacc[nt][0] *= f0; oacc[nt][1] *= f0;
            oacc[nt][2] *= f1; oacc[nt][3] *= f1;
        }

        // P = exp(S - m) -> fp16 smem; row sums
        float rs0 = 0.f, rs1 = 0.f;
        #pragma unroll
        for (int nt = 0; nt < 16; nt++) {
            float p0 = __expf(sacc[nt][0] - mnew0);
            float p1 = __expf(sacc[nt][1] - mnew0);
            float p2 = __expf(sacc[nt][2] - mnew1);
            float p3 = __expf(sacc[nt][3] - mnew1);
            rs0 += p0 + p1; rs1 += p2 + p3;
            *(__half2*)&Pw[gid * FP_STRIDE + nt * 8 + qid * 2] = __floats2half2_rn(p0, p1);
            *(__half2*)&Pw[(gid + 8) * FP_STRIDE + nt * 8 + qid * 2] = __floats2half2_rn(p2, p3);
        }
        rs0 += __shfl_xor_sync(0xffffffffu, rs0, 1);
        rs0 += __shfl_xor_sync(0xffffffffu, rs0, 2);
        rs1 += __shfl_xor_sync(0xffffffffu, rs1, 1);
        rs1 += __shfl_xor_sync(0xffffffffu, rs1, 2);
        l_i[0] += rs0; l_i[1] += rs1;

        __syncwarp();

        // O += P @ V
        #pragma unroll
        for (int kk2 = 0; kk2 < 8; kk2++) {
            uint32_t ap[4];
            const uint32_t* p0 = (const uint32_t*)(Pw + gid * FP_STRIDE);
            const uint32_t* p1 = (const uint32_t*)(Pw + (gid + 8) * FP_STRIDE);
            int w0 = kk2 * 8 + qid;
            ap[0] = p0[w0]; ap[1] = p1[w0]; ap[2] = p0[w0 + 4]; ap[3] = p1[w0 + 4];
            #pragma unroll
            for (int ntp = 0; ntp < 4; ntp++) {
                int vrow = kk2 * 16 + (t4 & 1) * 8 + r8;
                int vcol = ntp * 16 + (t4 >> 1) * 8;
                uint32_t addr = vbase + (uint32_t)(vrow * FQ_STRIDE + vcol) * 2u;
                uint32_t r0, r1, r2, r3;
                asm volatile(
                    "ldmatrix.sync.aligned.m8n8.x4.trans.shared.b16 {%0,%1,%2,%3}, [%4];"
                    : "=r"(r0), "=r"(r1), "=r"(r2), "=r"(r3) : "r"(addr));
                mma16(oacc[2 * ntp],     ap, r0, r1);
                mma16(oacc[2 * ntp + 1], ap, r2, r3);
            }
        }
        __syncthreads();   // all warps done reading cur before it is refilled next iter
    }

    float inv0 = 1.f / l_i[0];
    float inv1 = 1.f / l_i[1];
    __half2* C = (__half2*)(olin + (size_t)b * SEQ * DIM + h * HD);
    int row = m0 + warp * 16 + gid;
    #pragma unroll
    for (int nt = 0; nt < 8; nt++) {
        int col = nt * 8 + qid * 2;
        C[((size_t)row * DIM + col) >> 1] =
            __floats2half2_rn(oacc[nt][0] * inv0, oacc[nt][1] * inv0);
        C[((size_t)(row + 8) * DIM + col) >> 1] =
            __floats2half2_rn(oacc[nt][2] * inv1, oacc[nt][3] * inv1);
    }
}

// ---------------- launch ----------------
extern "C" void kernel_launch(void* const* d_in, const int* in_sizes, int n_in,
                              void* d_out, int out_size) {
    const float* x       = (const float*)d_in[0];
    const float* n1g     = (const float*)d_in[1];
    const float* n1b     = (const float*)d_in[2];
    const float* qkv_w   = (const float*)d_in[3];
    const float* qkv_b   = (const float*)d_in[4];
    const float* proj_w  = (const float*)d_in[5];
    const float* proj_b  = (const float*)d_in[6];
    const float* n2g     = (const float*)d_in[7];
    const float* n2b     = (const float*)d_in[8];
    const float* fc1_w   = (const float*)d_in[9];
    const float* fc1_b   = (const float*)d_in[10];
    const float* fc2_w   = (const float*)d_in[11];
    const float* fc2_b   = (const float*)d_in[12];
    float* out = (float*)d_out;

    __half *h1h, *h2h, *olinh, *h3h, *qkvh, *qkvwh, *projwh, *fc1wh, *fc2wh;
    float *x2;
    cudaGetSymbolAddress((void**)&h1h,    g_h1h);
    cudaGetSymbolAddress((void**)&h2h,    g_h2h);
    cudaGetSymbolAddress((void**)&olinh,  g_olinh);
    cudaGetSymbolAddress((void**)&h3h,    g_h3h);
    cudaGetSymbolAddress((void**)&qkvh,   g_qkvh);
    cudaGetSymbolAddress((void**)&x2,     g_x2);
    cudaGetSymbolAddress((void**)&qkvwh,  g_qkvwh);
    cudaGetSymbolAddress((void**)&projwh, g_projwh);
    cudaGetSymbolAddress((void**)&fc1wh,  g_fc1wh);
    cudaGetSymbolAddress((void**)&fc2wh,  g_fc2wh);

    cudaFuncSetAttribute(hgemm_tn_kernel<EPI_BIAS, 1>,
                         cudaFuncAttributeMaxDynamicSharedMemorySize, GEMM_SMEM);
    cudaFuncSetAttribute(hgemm_tn_kernel<EPI_BIAS_RES, 0>,
                         cudaFuncAttributeMaxDynamicSharedMemorySize, GEMM_SMEM);
    cudaFuncSetAttribute(hgemm_tn_kernel<EPI_BIAS_GELU, 1>,
                         cudaFuncAttributeMaxDynamicSharedMemorySize, GEMM_SMEM);
    cudaFuncSetAttribute(flash_kernel,
                         cudaFuncAttributeMaxDynamicSharedMemorySize, FLASH_SMEM);

    // 0) all weights fp32 -> fp16, one launch
    const int n0 = QKVDIM*DIM/4, n1 = DIM*DIM/4, n2 = HIDDEN*DIM/4, n3 = DIM*HIDDEN/4;
    cvt_all<<<(n0+n1+n2+n3 + 255)/256, 256>>>(
        (const float4*)qkv_w,  (__half2*)qkvwh,  n0,
        (const float4*)proj_w, (__half2*)projwh, n1,
        (const float4*)fc1_w,  (__half2*)fc1wh,  n2,
        (const float4*)fc2_w,  (__half2*)fc2wh,  n3);

    // 1) LN1 -> fp16
    ln_kernel<<<TOK, 256>>>(x, n1g, n1b, h1h);
    // 2) QKV = h1 @ qkv_w^T + b  (fp16 out)
    hgemm_tn_kernel<EPI_BIAS, 1><<<dim3(QKVDIM/128, TOK/128), 128, GEMM_SMEM>>>(
        h1h, DIM, qkvwh, DIM, qkvh, QKVDIM, DIM, qkv_b, nullptr, 0);
    // 3) fused fp16 attention -> olin (fp16)
    flash_kernel<<<dim3(SEQ/128, NBH), 256, FLASH_SMEM>>>(qkvh, olinh);
    // 4) x2 = x + olin @ proj_w^T + b (fp32)
    hgemm_tn_kernel<EPI_BIAS_RES, 0><<<dim3(DIM/128, TOK/128), 128, GEMM_SMEM>>>(
        olinh, DIM, projwh, DIM, x2, DIM, DIM, proj_b, x, DIM);
    // 5) LN2 -> fp16
    ln_kernel<<<TOK, 256>>>(x2, n2g, n2b, h2h);
    // 6) h3 = gelu(h2 @ fc1_w^T + b) (fp16 out)
    hgemm_tn_kernel<EPI_BIAS_GELU, 1><<<dim3(HIDDEN/128, TOK/128), 128, GEMM_SMEM>>>(
        h2h, DIM, fc1wh, DIM, h3h, HIDDEN, DIM, fc1_b, nullptr, 0);
    // 7) out = x2 + h3 @ fc2_w^T + b (fp32)
    hgemm_tn_kernel<EPI_BIAS_RES, 0><<<dim3(DIM/128, TOK/128), 128, GEMM_SMEM>>>(
        h3h, HIDDEN, fc2wh, HIDDEN, out, DIM, HIDDEN, fc2_b, x2, DIM);
}

// round 11
// speedup vs baseline: 1.8879x; 1.0277x over previous
#include <cuda_runtime.h>
#include <cuda_fp16.h>
#include <math.h>
#include <stdint.h>

// Problem dims
#define DIM     768
#define HEADS   12
#define HD      64
#define HIDDEN  3072
#define SEQ     1024
#define BATCHN  8
#define TOK     (BATCHN*SEQ)   // 8192
#define QKVDIM  (3*DIM)        // 2304
#define NBH     (BATCHN*HEADS) // 96

// fp16 GEMM tiling
#define BKH      64
#define HSTRIDE  72
#define STAGE_H  (128 * HSTRIDE)
#define GEMM_SMEM (2 * 2 * STAGE_H * 2)    // 73728 B -> 2 CTAs/SM

// fp16 flash smem (halves): Q | K | V | P(8 warps x 16 x 72)
#define FQ_STRIDE 72
#define FP_STRIDE 72
#define FTILE_H   (128 * FQ_STRIDE)
#define FLASH_SMEM ((3 * FTILE_H + 8 * 16 * FP_STRIDE) * 2)   // 73728 B -> 2 CTAs/SM

// ---------------- scratch ----------------
__device__ __half g_h1h[TOK*DIM];
__device__ __half g_h2h[TOK*DIM];
__device__ __half g_olinh[TOK*DIM];
__device__ __half g_h3h[(size_t)TOK*HIDDEN];
__device__ __half g_qkvh[(size_t)TOK*QKVDIM];
__device__ float  g_x2[TOK*DIM];
__device__ __half g_qkvwh[QKVDIM*DIM];
__device__ __half g_projwh[DIM*DIM];
__device__ __half g_fc1wh[HIDDEN*DIM];
__device__ __half g_fc2wh[DIM*HIDDEN];

// ---------------- helpers ----------------
__device__ __forceinline__ void mma16(float* d, const uint32_t* a, uint32_t b0, uint32_t b1) {
    asm volatile(
        "mma.sync.aligned.m16n8k16.row.col.f32.f16.f16.f32 "
        "{%0,%1,%2,%3}, {%4,%5,%6,%7}, {%8,%9}, {%0,%1,%2,%3};"
        : "+f"(d[0]), "+f"(d[1]), "+f"(d[2]), "+f"(d[3])
        : "r"(a[0]), "r"(a[1]), "r"(a[2]), "r"(a[3]), "r"(b0), "r"(b1));
}
__device__ __forceinline__ float gelu1(float x) {
    return 0.5f * x * (1.f + erff(x * 0.70710678118654752f));
}
__device__ __forceinline__ void cp16h(__half* dst, const __half* src) {
    unsigned d = (unsigned)__cvta_generic_to_shared(dst);
    asm volatile("cp.async.cg.shared.global [%0], [%1], 16;\n" :: "r"(d), "l"(src));
}
__device__ __forceinline__ void cp_commit() {
    asm volatile("cp.async.commit_group;\n");
}
template<int N>
__device__ __forceinline__ void cp_wait() {
    asm volatile("cp.async.wait_group %0;\n" :: "n"(N));
}

// ---------------- fused fp32 -> fp16 converter ----------------
__global__ void cvt_all(const float4* __restrict__ s0, __half2* __restrict__ d0, int n0,
                        const float4* __restrict__ s1, __half2* __restrict__ d1, int n1,
                        const float4* __restrict__ s2, __half2* __restrict__ d2, int n2,
                        const float4* __restrict__ s3, __half2* __restrict__ d3, int n3) {
    int i = blockIdx.x * blockDim.x + threadIdx.x;
    const float4* s; __half2* d;
    if (i < n0) { s = s0; d = d0; }
    else if ((i -= n0) < n1) { s = s1; d = d1; }
    else if ((i -= n1) < n2) { s = s2; d = d2; }
    else if ((i -= n2) < n3) { s = s3; d = d3; }
    else return;
    float4 v = s[i];
    d[2*i]   = __floats2half2_rn(v.x, v.y);
    d[2*i+1] = __floats2half2_rn(v.z, v.w);
}

// ---------------- LayerNorm (fp32 in, fp16 out) ----------------
__global__ void ln_kernel(const float* __restrict__ in,
                          const float* __restrict__ gam,
                          const float* __restrict__ bet,
                          __half* __restrict__ out) {
    int row = blockIdx.x;
    int t = threadIdx.x;
    const float* x = in + (size_t)row * DIM;
    float v0 = x[t], v1 = x[t + 256], v2 = x[t + 512];
    float s  = v0 + v1 + v2;
    float sq = v0*v0 + v1*v1 + v2*v2;
    __shared__ float redS[8], redQ[8];
    #pragma unroll
    for (int o = 16; o > 0; o >>= 1) {
        s  += __shfl_xor_sync(0xffffffffu, s,  o);
        sq += __shfl_xor_sync(0xffffffffu, sq, o);
    }
    if ((t & 31) == 0) { redS[t >> 5] = s; redQ[t >> 5] = sq; }
    __syncthreads();
    if (t < 32) {
        float s2 = (t < 8) ? redS[t] : 0.f;
        float q2 = (t < 8) ? redQ[t] : 0.f;
        #pragma unroll
        for (int o = 4; o > 0; o >>= 1) {
            s2 += __shfl_xor_sync(0xffffffffu, s2, o);
            q2 += __shfl_xor_sync(0xffffffffu, q2, o);
        }
        if (t == 0) { redS[0] = s2; redQ[0] = q2; }
    }
    __syncthreads();
    float mu  = redS[0] * (1.0f / DIM);
    float var = redQ[0] * (1.0f / DIM) - mu * mu;
    float inv = rsqrtf(var + 1e-5f);
    __half* o = out + (size_t)row * DIM;
    o[t]       = __float2half((v0 - mu) * inv * gam[t]       + bet[t]);
    o[t + 256] = __float2half((v1 - mu) * inv * gam[t + 256] + bet[t + 256]);
    o[t + 512] = __float2half((v2 - mu) * inv * gam[t + 512] + bet[t + 512]);
}

// ---------------- FP16 MMA GEMM (TN): 256 thr, warp 64x32, 2 CTAs/SM ----------------
enum { EPI_BIAS = 1, EPI_BIAS_RES = 2, EPI_BIAS_GELU = 3 };

template<int EPI, int OUTH>
__global__ __launch_bounds__(256, 2)
void hgemm_tn_kernel(const __half* __restrict__ A, int lda,
                     const __half* __restrict__ W, int ldw,
                     void* __restrict__ Cv, int ldc, int K,
                     const float* __restrict__ bias,
                     const float* __restrict__ res, int ldres) {
    extern __shared__ __half smh[];
    const int m0 = blockIdx.y * 128, n0 = blockIdx.x * 128;
    const int tid  = threadIdx.x;
    const int lane = tid & 31;
    const int warp = tid >> 5;
    const int m0w  = (warp >> 2) * 64;   // 2 warps along M
    const int n0w  = (warp & 3) * 32;    // 4 warps along N
    const int gid  = lane >> 2;
    const int qid  = lane & 3;

    // loader: 256 threads, 4 rows per array each
    const int crow0 = tid >> 3;          // 0..31
    const int cgr   = tid & 7;

    float acc[4][4][4];
    #pragma unroll
    for (int i = 0; i < 4; i++)
        #pragma unroll
        for (int j = 0; j < 4; j++)
            #pragma unroll
            for (int r = 0; r < 4; r++) acc[i][j][r] = 0.f;

    const int nch = K / BKH;

    auto load_chunk = [&](int j) {
        __half* as = smh + (j & 1) * 2 * STAGE_H;
        __half* ws = as + STAGE_H;
        const __half* Aj = A + (size_t)m0 * lda + j * BKH + cgr * 8;
        const __half* Wj = W + (size_t)n0 * ldw + j * BKH + cgr * 8;
        #pragma unroll
        for (int r = 0; r < 4; r++) {
            int row = crow0 + r * 32;
            cp16h(&as[row * HSTRIDE + cgr * 8], Aj + (size_t)row * lda);
            cp16h(&ws[row * HSTRIDE + cgr * 8], Wj + (size_t)row * ldw);
        }
    };

    load_chunk(0);
    cp_commit();

    for (int i = 0; i < nch; i++) {
        cp_wait<0>();
        __syncthreads();

        if (i + 1 < nch) {
            load_chunk(i + 1);
            cp_commit();
        }

        const __half* As = smh + (i & 1) * 2 * STAGE_H;
        const __half* Ws = As + STAGE_H;
        #pragma unroll
        for (int ks = 0; ks < 4; ks++) {
            const int w0 = ks * 8 + qid;
            uint32_t af[4][4];
            #pragma unroll
            for (int mt = 0; mt < 4; mt++) {
                const uint32_t* p0 = (const uint32_t*)(As + (m0w + mt * 16 + gid) * HSTRIDE);
                const uint32_t* p1 = (const uint32_t*)(As + (m0w + mt * 16 + gid + 8) * HSTRIDE);
                af[mt][0] = p0[w0];
                af[mt][1] = p1[w0];
                af[mt][2] = p0[w0 + 4];
                af[mt][3] = p1[w0 + 4];
            }
            #pragma unroll
            for (int nt = 0; nt < 4; nt++) {
                const uint32_t* pb = (const uint32_t*)(Ws + (n0w + nt * 8 + gid) * HSTRIDE);
                uint32_t b0 = pb[w0];
                uint32_t b1 = pb[w0 + 4];
                #pragma unroll
                for (int mt = 0; mt < 4; mt++)
                    mma16(acc[mt][nt], af[mt], b0, b1);
            }
        }
    }

    #pragma unroll
    for (int mt = 0; mt < 4; mt++) {
        #pragma unroll
        for (int nt = 0; nt < 4; nt++) {
            int row = m0 + m0w + mt * 16 + gid;
            int col = n0 + n0w + nt * 8 + qid * 2;
            float2 v0, v1;
            v0.x = acc[mt][nt][0]; v0.y = acc[mt][nt][1];
            v1.x = acc[mt][nt][2]; v1.y = acc[mt][nt][3];
            {
                float2 bb = *(const float2*)(bias + col);
                v0.x += bb.x; v0.y += bb.y; v1.x += bb.x; v1.y += bb.y;
            }
            if (EPI == EPI_BIAS_RES) {
                float2 r0 = *(const float2*)(res + (size_t)row * ldres + col);
                float2 r1 = *(const float2*)(res + (size_t)(row + 8) * ldres + col);
                v0.x += r0.x; v0.y += r0.y; v1.x += r1.x; v1.y += r1.y;
            }
            if (EPI == EPI_BIAS_GELU) {
                v0.x = gelu1(v0.x); v0.y = gelu1(v0.y);
                v1.x = gelu1(v1.x); v1.y = gelu1(v1.y);
            }
            if (OUTH) {
                __half2* C = (__half2*)Cv;
                C[((size_t)row * ldc + col) >> 1]       = __floats2half2_rn(v0.x, v0.y);
                C[((size_t)(row + 8) * ldc + col) >> 1] = __floats2half2_rn(v1.x, v1.y);
            } else {
                float* C = (float*)Cv;
                *(float2*)(C + (size_t)row * ldc + col) = v0;
                *(float2*)(C + (size_t)(row + 8) * ldc + col) = v1;
            }
        }
    }
}

// ---------------- FP16 flash attention: 64-key softmax halves, 2 CTAs/SM ----------------
__global__ __launch_bounds__(256, 2)
void flash_kernel(const __half* __restrict__ qkv, __half* __restrict__ olin) {
    extern __shared__ __half smf[];
    __half* Qs = smf;
    __half* Ks = Qs + FTILE_H;
    __half* Vs = Ks + FTILE_H;
    __half* Ps = Vs + FTILE_H;

    const int bh = blockIdx.y;
    const int b = bh / HEADS, h = bh % HEADS;
    const int m0 = blockIdx.x * 128;
    const __half* Qg = qkv + (size_t)b * SEQ * QKVDIM + h * HD;
    const __half* Kg = Qg + DIM;
    const __half* Vg = Qg + 2 * DIM;

    const int tid = threadIdx.x, lane = tid & 31, warp = tid >> 5;
    const int gid = lane >> 2, qid = lane & 3;

    // Q tile
    #pragma unroll
    for (int i = 0; i < 4; i++) {
        int f = i * 256 + tid;
        int r = f >> 3, c8 = (f & 7) * 8;
        cp16h(&Qs[r * FQ_STRIDE + c8], Qg + (size_t)(m0 + r) * QKVDIM + c8);
    }
    cp_commit();
    cp_wait<0>();
    __syncthreads();

    // preload Q fragments, pre-scaled by 1/8
    const __half2 kscale = __floats2half2_rn(0.125f, 0.125f);
    uint32_t qf[4][4];
    {
        const uint32_t* q0 = (const uint32_t*)(Qs + (warp * 16 + gid) * FQ_STRIDE);
        const uint32_t* q1 = (const uint32_t*)(Qs + (warp * 16 + gid + 8) * FQ_STRIDE);
        #pragma unroll
        for (int kk = 0; kk < 4; kk++) {
            int w0 = kk * 8 + qid;
            uint32_t w;
            w = q0[w0];     { __half2 t = __hmul2(*(__half2*)&w, kscale); qf[kk][0] = *(uint32_t*)&t; }
            w = q1[w0];     { __half2 t = __hmul2(*(__half2*)&w, kscale); qf[kk][1] = *(uint32_t*)&t; }
            w = q0[w0 + 4]; { __half2 t = __hmul2(*(__half2*)&w, kscale); qf[kk][2] = *(uint32_t*)&t; }
            w = q1[w0 + 4]; { __half2 t = __hmul2(*(__half2*)&w, kscale); qf[kk][3] = *(uint32_t*)&t; }
        }
    }

    float m_i[2] = {-1e30f, -1e30f};
    float l_i[2] = {0.f, 0.f};
    float oacc[8][4];
    #pragma unroll
    for (int nt = 0; nt < 8; nt++)
        #pragma unroll
        for (int r = 0; r < 4; r++) oacc[nt][r] = 0.f;

    __half* Pw = Ps + warp * 16 * FP_STRIDE;
    const uint32_t vbase = (uint32_t)__cvta_generic_to_shared(Vs);
    const int t4 = lane >> 3, r8 = lane & 7;

    for (int kc = 0; kc < 8; kc++) {
        __syncthreads();   // previous chunk fully consumed
        const __half* Kc = Kg + (size_t)(kc * 128) * QKVDIM;
        const __half* Vc = Vg + (size_t)(kc * 128) * QKVDIM;
        #pragma unroll
        for (int i = 0; i < 4; i++) {
            int f = i * 256 + tid;
            int r = f >> 3, c8 = (f & 7) * 8;
            cp16h(&Ks[r * FQ_STRIDE + c8], Kc + (size_t)r * QKVDIM + c8);
            cp16h(&Vs[r * FQ_STRIDE + c8], Vc + (size_t)r * QKVDIM + c8);
        }
        cp_commit();
        cp_wait<0>();
        __syncthreads();

        // two 64-key halves with online softmax each (keeps regs <= 128)
        #pragma unroll
        for (int half = 0; half < 2; half++) {
            const int koff = half * 64;

            float sacc[8][4];
            #pragma unroll
            for (int nt = 0; nt < 8; nt++)
                #pragma unroll
                for (int r = 0; r < 4; r++) sacc[nt][r] = 0.f;
            #pragma unroll
            for (int kk = 0; kk < 4; kk++) {
                const int w0 = kk * 8 + qid;
                #pragma unroll
                for (int nt = 0; nt < 8; nt++) {
                    const uint32_t* pb =
                        (const uint32_t*)(Ks + (koff + nt * 8 + gid) * FQ_STRIDE);
                    mma16(sacc[nt], qf[kk], pb[w0], pb[w0 + 4]);
                }
            }

            float mx0 = -1e30f, mx1 = -1e30f;
            #pragma unroll
            for (int nt = 0; nt < 8; nt++) {
                mx0 = fmaxf(mx0, fmaxf(sacc[nt][0], sacc[nt][1]));
                mx1 = fmaxf(mx1, fmaxf(sacc[nt][2], sacc[nt][3]));
            }
            mx0 = fmaxf(mx0, __shfl_xor_sync(0xffffffffu, mx0, 1));
            mx0 = fmaxf(mx0, __shfl_xor_sync(0xffffffffu, mx0, 2));
            mx1 = fmaxf(mx1, __shfl_xor_sync(0xffffffffu, mx1, 1));
            mx1 = fmaxf(mx1, __shfl_xor_sync(0xffffffffu, mx1, 2));

            float mnew0 = fmaxf(m_i[0], mx0);
            float mnew1 = fmaxf(m_i[1], mx1);
            float f0 = __expf(m_i[0] - mnew0);
            float f1 = __expf(m_i[1] - mnew1);
            m_i[0] = mnew0; m_i[1] = mnew1;
            l_i[0] *= f0;   l_i[1] *= f1;
            #pragma unroll
            for (int nt = 0; nt < 8; nt++) {
                oacc[nt][0] *= f0; oacc[nt][1] *= f0;
                oacc[nt][2] *= f1; oacc[nt][3] *= f1;
            }

            float rs0 = 0.f, rs1 = 0.f;
            #pragma unroll
            for (int nt = 0; nt < 8; nt++) {
                float p0 = __expf(sacc[nt][0] - mnew0);
                float p1 = __expf(sacc[nt][1] - mnew0);
                float p2 = __expf(sacc[nt][2] - mnew1);
                float p3 = __expf(sacc[nt][3] - mnew1);
                rs0 += p0 + p1; rs1 += p2 + p3;
                *(__half2*)&Pw[gid * FP_STRIDE + nt * 8 + qid * 2] = __floats2half2_rn(p0, p1);
                *(__half2*)&Pw[(gid + 8) * FP_STRIDE + nt * 8 + qid * 2] = __floats2half2_rn(p2, p3);
            }
            rs0 += __shfl_xor_sync(0xffffffffu, rs0, 1);
            rs0 += __shfl_xor_sync(0xffffffffu, rs0, 2);
            rs1 += __shfl_xor_sync(0xffffffffu, rs1, 1);
            rs1 += __shfl_xor_sync(0xffffffffu, rs1, 2);
            l_i[0] += rs0; l_i[1] += rs1;

            __syncwarp();

            // O += P(16x64) @ V[koff:koff+64, :]
            #pragma unroll
            for (int kk2 = 0; kk2 < 4; kk2++) {
                uint32_t ap[4];
                const uint32_t* p0 = (const uint32_t*)(Pw + gid * FP_STRIDE);
                const uint32_t* p1 = (const uint32_t*)(Pw + (gid + 8) * FP_STRIDE);
                int w0 = kk2 * 8 + qid;
                ap[0] = p0[w0]; ap[1] = p1[w0]; ap[2] = p0[w0 + 4]; ap[3] = p1[w0 + 4];
                #pragma unroll
                for (int ntp = 0; ntp < 4; ntp++) {
                    int vrow = koff + kk2 * 16 + (t4 & 1) * 8 + r8;
                    int vcol = ntp * 16 + (t4 >> 1) * 8;
                    uint32_t addr = vbase + (uint32_t)(vrow * FQ_STRIDE + vcol) * 2u;
                    uint32_t r0, r1, r2, r3;
                    asm volatile(
                        "ldmatrix.sync.aligned.m8n8.x4.trans.shared.b16 {%0,%1,%2,%3}, [%4];"
                        : "=r"(r0), "=r"(r1), "=r"(r2), "=r"(r3) : "r"(addr));
                    mma16(oacc[2 * ntp],     ap, r0, r1);
                    mma16(oacc[2 * ntp + 1], ap, r2, r3);
                }
            }
            __syncwarp();
        }
    }

    float inv0 = 1.f / l_i[0];
    float inv1 = 1.f / l_i[1];
    __half2* C = (__half2*)(olin + (size_t)b * SEQ * DIM + h * HD);
    int row = m0 + warp * 16 + gid;
    #pragma unroll
    for (int nt = 0; nt < 8; nt++) {
        int col = nt * 8 + qid * 2;
        C[((size_t)row * DIM + col) >> 1] =
            __floats2half2_rn(oacc[nt][0] * inv0, oacc[nt][1] * inv0);
        C[((size_t)(row + 8) * DIM + col) >> 1] =
            __floats2half2_rn(oacc[nt][2] * inv1, oacc[nt][3] * inv1);
    }
}

// ---------------- launch ----------------
extern "C" void kernel_launch(void* const* d_in, const int* in_sizes, int n_in,
                              void* d_out, int out_size) {
    const float* x       = (const float*)d_in[0];
    const float* n1g     = (const float*)d_in[1];
    const float* n1b     = (const float*)d_in[2];
    const float* qkv_w   = (const float*)d_in[3];
    const float* qkv_b   = (const float*)d_in[4];
    const float* proj_w  = (const float*)d_in[5];
    const float* proj_b  = (const float*)d_in[6];
    const float* n2g     = (const float*)d_in[7];
    const float* n2b     = (const float*)d_in[8];
    const float* fc1_w   = (const float*)d_in[9];
    const float* fc1_b   = (const float*)d_in[10];
    const float* fc2_w   = (const float*)d_in[11];
    const float* fc2_b   = (const float*)d_in[12];
    float* out = (float*)d_out;

    __half *h1h, *h2h, *olinh, *h3h, *qkvh, *qkvwh, *projwh, *fc1wh, *fc2wh;
    float *x2;
    cudaGetSymbolAddress((void**)&h1h,    g_h1h);
    cudaGetSymbolAddress((void**)&h2h,    g_h2h);
    cudaGetSymbolAddress((void**)&olinh,  g_olinh);
    cudaGetSymbolAddress((void**)&h3h,    g_h3h);
    cudaGetSymbolAddress((void**)&qkvh,   g_qkvh);
    cudaGetSymbolAddress((void**)&x2,     g_x2);
    cudaGetSymbolAddress((void**)&qkvwh,  g_qkvwh);
    cudaGetSymbolAddress((void**)&projwh, g_projwh);
    cudaGetSymbolAddress((void**)&fc1wh,  g_fc1wh);
    cudaGetSymbolAddress((void**)&fc2wh,  g_fc2wh);

    cudaFuncSetAttribute(hgemm_tn_kernel<EPI_BIAS, 1>,
                         cudaFuncAttributeMaxDynamicSharedMemorySize, GEMM_SMEM);
    cudaFuncSetAttribute(hgemm_tn_kernel<EPI_BIAS_RES, 0>,
                         cudaFuncAttributeMaxDynamicSharedMemorySize, GEMM_SMEM);
    cudaFuncSetAttribute(hgemm_tn_kernel<EPI_BIAS_GELU, 1>,
                         cudaFuncAttributeMaxDynamicSharedMemorySize, GEMM_SMEM);
    cudaFuncSetAttribute(flash_kernel,
                         cudaFuncAttributeMaxDynamicSharedMemorySize, FLASH_SMEM);

    // 0) all weights fp32 -> fp16, one launch
    const int n0 = QKVDIM*DIM/4, n1 = DIM*DIM/4, n2 = HIDDEN*DIM/4, n3 = DIM*HIDDEN/4;
    cvt_all<<<(n0+n1+n2+n3 + 255)/256, 256>>>(
        (const float4*)qkv_w,  (__half2*)qkvwh,  n0,
        (const float4*)proj_w, (__half2*)projwh, n1,
        (const float4*)fc1_w,  (__half2*)fc1wh,  n2,
        (const float4*)fc2_w,  (__half2*)fc2wh,  n3);

    // 1) LN1 -> fp16
    ln_kernel<<<TOK, 256>>>(x, n1g, n1b, h1h);
    // 2) QKV = h1 @ qkv_w^T + b  (fp16 out)
    hgemm_tn_kernel<EPI_BIAS, 1><<<dim3(QKVDIM/128, TOK/128), 256, GEMM_SMEM>>>(
        h1h, DIM, qkvwh, DIM, qkvh, QKVDIM, DIM, qkv_b, nullptr, 0);
    // 3) fused fp16 attention -> olin (fp16)
    flash_kernel<<<dim3(SEQ/128, NBH), 256, FLASH_SMEM>>>(qkvh, olinh);
    // 4) x2 = x + olin @ proj_w^T + b (fp32)
    hgemm_tn_kernel<EPI_BIAS_RES, 0><<<dim3(DIM/128, TOK/128), 256, GEMM_SMEM>>>(
        olinh, DIM, projwh, DIM, x2, DIM, DIM, proj_b, x, DIM);
    // 5) LN2 -> fp16
    ln_kernel<<<TOK, 256>>>(x2, n2g, n2b, h2h);
    // 6) h3 = gelu(h2 @ fc1_w^T + b) (fp16 out)
    hgemm_tn_kernel<EPI_BIAS_GELU, 1><<<dim3(HIDDEN/128, TOK/128), 256, GEMM_SMEM>>>(
        h2h, DIM, fc1wh, DIM, h3h, HIDDEN, DIM, fc1_b, nullptr, 0);
    // 7) out = x2 + h3 @ fc2_w^T + b (fp32)
    hgemm_tn_kernel<EPI_BIAS_RES, 0><<<dim3(DIM/128, TOK/128), 256, GEMM_SMEM>>>(
        h3h, HIDDEN, fc2wh, HIDDEN, out, DIM, HIDDEN, fc2_b, x2, DIM);
}

// round 12
// speedup vs baseline: 2.0346x; 1.0777x over previous
#include <cuda_runtime.h>
#include <cuda_fp16.h>
#include <math.h>
#include <stdint.h>

// Problem dims
#define DIM     768
#define HEADS   12
#define HD      64
#define HIDDEN  3072
#define SEQ     1024
#define BATCHN  8
#define TOK     (BATCHN*SEQ)   // 8192
#define QKVDIM  (3*DIM)        // 2304
#define NBH     (BATCHN*HEADS) // 96

// fp16 GEMM tiling
#define BKH      64
#define HSTRIDE  72
#define STAGE_H  (128 * HSTRIDE)
#define GEMM_SMEM (2 * 2 * STAGE_H * 2)    // 73728 B -> 2 CTAs/SM

// fp16 flash smem (halves): Q | K | V | P(8 warps x 16 x 72)
#define FQ_STRIDE 72
#define FP_STRIDE 72
#define FTILE_H   (128 * FQ_STRIDE)
#define FLASH_SMEM ((3 * FTILE_H + 8 * 16 * FP_STRIDE) * 2)   // 73728 B -> 2 CTAs/SM

#define LOG2E 1.44269504088896f

// ---------------- scratch ----------------
__device__ __half g_h1h[TOK*DIM];
__device__ __half g_h2h[TOK*DIM];
__device__ __half g_olinh[TOK*DIM];
__device__ __half g_h3h[(size_t)TOK*HIDDEN];
__device__ __half g_qkvh[(size_t)TOK*QKVDIM];
__device__ float  g_x2[TOK*DIM];
__device__ __half g_qkvwh[QKVDIM*DIM];
__device__ __half g_projwh[DIM*DIM];
__device__ __half g_fc1wh[HIDDEN*DIM];
__device__ __half g_fc2wh[DIM*HIDDEN];

// ---------------- helpers ----------------
__device__ __forceinline__ void mma16(float* d, const uint32_t* a, uint32_t b0, uint32_t b1) {
    asm volatile(
        "mma.sync.aligned.m16n8k16.row.col.f32.f16.f16.f32 "
        "{%0,%1,%2,%3}, {%4,%5,%6,%7}, {%8,%9}, {%0,%1,%2,%3};"
        : "+f"(d[0]), "+f"(d[1]), "+f"(d[2]), "+f"(d[3])
        : "r"(a[0]), "r"(a[1]), "r"(a[2]), "r"(a[3]), "r"(b0), "r"(b1));
}
__device__ __forceinline__ void ldsm4(uint32_t* r, uint32_t addr) {
    asm volatile("ldmatrix.sync.aligned.m8n8.x4.shared.b16 {%0,%1,%2,%3}, [%4];"
        : "=r"(r[0]), "=r"(r[1]), "=r"(r[2]), "=r"(r[3]) : "r"(addr));
}
__device__ __forceinline__ float gelu1(float x) {
    return 0.5f * x * (1.f + erff(x * 0.70710678118654752f));
}
__device__ __forceinline__ void cp16h(__half* dst, const __half* src) {
    unsigned d = (unsigned)__cvta_generic_to_shared(dst);
    asm volatile("cp.async.cg.shared.global [%0], [%1], 16;\n" :: "r"(d), "l"(src));
}
__device__ __forceinline__ void cp_commit() {
    asm volatile("cp.async.commit_group;\n");
}
template<int N>
__device__ __forceinline__ void cp_wait() {
    asm volatile("cp.async.wait_group %0;\n" :: "n"(N));
}

// ---------------- fused fp32 -> fp16 converter ----------------
__global__ void cvt_all(const float4* __restrict__ s0, __half2* __restrict__ d0, int n0,
                        const float4* __restrict__ s1, __half2* __restrict__ d1, int n1,
                        const float4* __restrict__ s2, __half2* __restrict__ d2, int n2,
                        const float4* __restrict__ s3, __half2* __restrict__ d3, int n3) {
    int i = blockIdx.x * blockDim.x + threadIdx.x;
    const float4* s; __half2* d;
    if (i < n0) { s = s0; d = d0; }
    else if ((i -= n0) < n1) { s = s1; d = d1; }
    else if ((i -= n1) < n2) { s = s2; d = d2; }
    else if ((i -= n2) < n3) { s = s3; d = d3; }
    else return;
    float4 v = s[i];
    d[2*i]   = __floats2half2_rn(v.x, v.y);
    d[2*i+1] = __floats2half2_rn(v.z, v.w);
}

// ---------------- LayerNorm (fp32 in, fp16 out) ----------------
__global__ void ln_kernel(const float* __restrict__ in,
                          const float* __restrict__ gam,
                          const float* __restrict__ bet,
                          __half* __restrict__ out) {
    int row = blockIdx.x;
    int t = threadIdx.x;
    const float* x = in + (size_t)row * DIM;
    float v0 = x[t], v1 = x[t + 256], v2 = x[t + 512];
    float s  = v0 + v1 + v2;
    float sq = v0*v0 + v1*v1 + v2*v2;
    __shared__ float redS[8], redQ[8];
    #pragma unroll
    for (int o = 16; o > 0; o >>= 1) {
        s  += __shfl_xor_sync(0xffffffffu, s,  o);
        sq += __shfl_xor_sync(0xffffffffu, sq, o);
    }
    if ((t & 31) == 0) { redS[t >> 5] = s; redQ[t >> 5] = sq; }
    __syncthreads();
    if (t < 32) {
        float s2 = (t < 8) ? redS[t] : 0.f;
        float q2 = (t < 8) ? redQ[t] : 0.f;
        #pragma unroll
        for (int o = 4; o > 0; o >>= 1) {
            s2 += __shfl_xor_sync(0xffffffffu, s2, o);
            q2 += __shfl_xor_sync(0xffffffffu, q2, o);
        }
        if (t == 0) { redS[0] = s2; redQ[0] = q2; }
    }
    __syncthreads();
    float mu  = redS[0] * (1.0f / DIM);
    float var = redQ[0] * (1.0f / DIM) - mu * mu;
    float inv = rsqrtf(var + 1e-5f);
    __half* o = out + (size_t)row * DIM;
    o[t]       = __float2half((v0 - mu) * inv * gam[t]       + bet[t]);
    o[t + 256] = __float2half((v1 - mu) * inv * gam[t + 256] + bet[t + 256]);
    o[t + 512] = __float2half((v2 - mu) * inv * gam[t + 512] + bet[t + 512]);
}

// ---------------- FP16 MMA GEMM (TN): 256 thr, warp 64x32, ldmatrix fragments ------
enum { EPI_BIAS = 1, EPI_BIAS_RES = 2, EPI_BIAS_GELU = 3 };

template<int EPI, int OUTH>
__global__ __launch_bounds__(256, 2)
void hgemm_tn_kernel(const __half* __restrict__ A, int lda,
                     const __half* __restrict__ W, int ldw,
                     void* __restrict__ Cv, int ldc, int K,
                     const float* __restrict__ bias,
                     const float* __restrict__ res, int ldres) {
    extern __shared__ __half smh[];
    const uint32_t smbase = (uint32_t)__cvta_generic_to_shared(smh);
    const int m0 = blockIdx.y * 128, n0 = blockIdx.x * 128;
    const int tid  = threadIdx.x;
    const int lane = tid & 31;
    const int warp = tid >> 5;
    const int m0w  = (warp >> 2) * 64;
    const int n0w  = (warp & 3) * 32;
    const int gid  = lane >> 2;
    const int qid  = lane & 3;
    const int i8   = lane >> 3;     // ldmatrix matrix id
    const int r8   = lane & 7;      // row within matrix

    const int crow0 = tid >> 3;
    const int cgr   = tid & 7;

    float acc[4][4][4];
    #pragma unroll
    for (int i = 0; i < 4; i++)
        #pragma unroll
        for (int j = 0; j < 4; j++)
            #pragma unroll
            for (int r = 0; r < 4; r++) acc[i][j][r] = 0.f;

    const int nch = K / BKH;

    auto load_chunk = [&](int j) {
        __half* as = smh + (j & 1) * 2 * STAGE_H;
        __half* ws = as + STAGE_H;
        const __half* Aj = A + (size_t)m0 * lda + j * BKH + cgr * 8;
        const __half* Wj = W + (size_t)n0 * ldw + j * BKH + cgr * 8;
        #pragma unroll
        for (int r = 0; r < 4; r++) {
            int row = crow0 + r * 32;
            cp16h(&as[row * HSTRIDE + cgr * 8], Aj + (size_t)row * lda);
            cp16h(&ws[row * HSTRIDE + cgr * 8], Wj + (size_t)row * ldw);
        }
    };

    load_chunk(0);
    cp_commit();

    for (int i = 0; i < nch; i++) {
        cp_wait<0>();
        __syncthreads();

        if (i + 1 < nch) {
            load_chunk(i + 1);
            cp_commit();
        }

        const uint32_t abase = smbase + ((i & 1) * 2 * STAGE_H) * 2;
        const uint32_t bbase = abase + STAGE_H * 2;
        #pragma unroll
        for (int ks = 0; ks < 4; ks++) {
            uint32_t af[4][4];
            #pragma unroll
            for (int mt = 0; mt < 4; mt++) {
                int row = m0w + mt * 16 + (i8 & 1) * 8 + r8;
                int kc  = ks * 16 + (i8 >> 1) * 8;
                ldsm4(af[mt], abase + (uint32_t)(row * HSTRIDE + kc) * 2u);
            }
            uint32_t bf[8];
            #pragma unroll
            for (int j = 0; j < 2; j++) {
                int nrow = n0w + (2 * j + (i8 >> 1)) * 8 + r8;
                int kc   = ks * 16 + (i8 & 1) * 8;
                ldsm4(&bf[4 * j], bbase + (uint32_t)(nrow * HSTRIDE + kc) * 2u);
            }
            #pragma unroll
            for (int nt = 0; nt < 4; nt++)
                #pragma unroll
                for (int mt = 0; mt < 4; mt++)
                    mma16(acc[mt][nt], af[mt], bf[nt * 2], bf[nt * 2 + 1]);
        }
    }

    #pragma unroll
    for (int mt = 0; mt < 4; mt++) {
        #pragma unroll
        for (int nt = 0; nt < 4; nt++) {
            int row = m0 + m0w + mt * 16 + gid;
            int col = n0 + n0w + nt * 8 + qid * 2;
            float2 v0, v1;
            v0.x = acc[mt][nt][0]; v0.y = acc[mt][nt][1];
            v1.x = acc[mt][nt][2]; v1.y = acc[mt][nt][3];
            {
                float2 bb = *(const float2*)(bias + col);
                v0.x += bb.x; v0.y += bb.y; v1.x += bb.x; v1.y += bb.y;
            }
            if (EPI == EPI_BIAS_RES) {
                float2 r0 = *(const float2*)(res + (size_t)row * ldres + col);
                float2 r1 = *(const float2*)(res + (size_t)(row + 8) * ldres + col);
                v0.x += r0.x; v0.y += r0.y; v1.x += r1.x; v1.y += r1.y;
            }
            if (EPI == EPI_BIAS_GELU) {
                v0.x = gelu1(v0.x); v0.y = gelu1(v0.y);
                v1.x = gelu1(v1.x); v1.y = gelu1(v1.y);
            }
            if (OUTH) {
                __half2* C = (__half2*)Cv;
                C[((size_t)row * ldc + col) >> 1]       = __floats2half2_rn(v0.x, v0.y);
                C[((size_t)(row + 8) * ldc + col) >> 1] = __floats2half2_rn(v1.x, v1.y);
            } else {
                float* C = (float*)Cv;
                *(float2*)(C + (size_t)row * ldc + col) = v0;
                *(float2*)(C + (size_t)(row + 8) * ldc + col) = v1;
            }
        }
    }
}

// ---------------- FP16 flash attention: ldmatrix fragments, exp2 softmax ----------
__global__ __launch_bounds__(256, 2)
void flash_kernel(const __half* __restrict__ qkv, __half* __restrict__ olin) {
    extern __shared__ __half smf[];
    __half* Qs = smf;
    __half* Ks = Qs + FTILE_H;
    __half* Vs = Ks + FTILE_H;
    __half* Ps = Vs + FTILE_H;

    const int bh = blockIdx.y;
    const int b = bh / HEADS, h = bh % HEADS;
    const int m0 = blockIdx.x * 128;
    const __half* Qg = qkv + (size_t)b * SEQ * QKVDIM + h * HD;
    const __half* Kg = Qg + DIM;
    const __half* Vg = Qg + 2 * DIM;

    const int tid = threadIdx.x, lane = tid & 31, warp = tid >> 5;
    const int gid = lane >> 2, qid = lane & 3;
    const int i8 = lane >> 3, r8 = lane & 7;
    const int t4 = lane >> 3;

    const uint32_t qbase = (uint32_t)__cvta_generic_to_shared(Qs);
    const uint32_t kbase = (uint32_t)__cvta_generic_to_shared(Ks);
    const uint32_t vbase = (uint32_t)__cvta_generic_to_shared(Vs);
    const uint32_t pbase = (uint32_t)__cvta_generic_to_shared(Ps) +
                           (uint32_t)(warp * 16 * FP_STRIDE) * 2u;

    // Q tile
    #pragma unroll
    for (int i = 0; i < 4; i++) {
        int f = i * 256 + tid;
        int r = f >> 3, c8 = (f & 7) * 8;
        cp16h(&Qs[r * FQ_STRIDE + c8], Qg + (size_t)(m0 + r) * QKVDIM + c8);
    }
    cp_commit();
    cp_wait<0>();
    __syncthreads();

    // preload Q fragments via ldmatrix, pre-scaled by 0.125*log2e (exp2 softmax)
    const __half2 kscale = __floats2half2_rn(0.125f * LOG2E, 0.125f * LOG2E);
    uint32_t qf[4][4];
    #pragma unroll
    for (int kk = 0; kk < 4; kk++) {
        int row = warp * 16 + (i8 & 1) * 8 + r8;
        int kc  = kk * 16 + (i8 >> 1) * 8;
        ldsm4(qf[kk], qbase + (uint32_t)(row * FQ_STRIDE + kc) * 2u);
        #pragma unroll
        for (int r = 0; r < 4; r++) {
            __half2 t = __hmul2(*(__half2*)&qf[kk][r], kscale);
            qf[kk][r] = *(uint32_t*)&t;
        }
    }

    float m_i[2] = {-1e30f, -1e30f};
    float l_i[2] = {0.f, 0.f};
    float oacc[8][4];
    #pragma unroll
    for (int nt = 0; nt < 8; nt++)
        #pragma unroll
        for (int r = 0; r < 4; r++) oacc[nt][r] = 0.f;

    __half* Pw = Ps + warp * 16 * FP_STRIDE;

    for (int kc = 0; kc < 8; kc++) {
        __syncthreads();
        const __half* Kc = Kg + (size_t)(kc * 128) * QKVDIM;
        const __half* Vc = Vg + (size_t)(kc * 128) * QKVDIM;
        #pragma unroll
        for (int i = 0; i < 4; i++) {
            int f = i * 256 + tid;
            int r = f >> 3, c8 = (f & 7) * 8;
            cp16h(&Ks[r * FQ_STRIDE + c8], Kc + (size_t)r * QKVDIM + c8);
            cp16h(&Vs[r * FQ_STRIDE + c8], Vc + (size_t)r * QKVDIM + c8);
        }
        cp_commit();
        cp_wait<0>();
        __syncthreads();

        // two 64-key halves with online softmax
        #pragma unroll
        for (int half = 0; half < 2; half++) {
            const int koff = half * 64;

            float sacc[8][4];
            #pragma unroll
            for (int nt = 0; nt < 8; nt++)
                #pragma unroll
                for (int r = 0; r < 4; r++) sacc[nt][r] = 0.f;
            #pragma unroll
            for (int kk = 0; kk < 4; kk++) {
                uint32_t bf[8];
                #pragma unroll
                for (int j = 0; j < 4; j += 2) {   // 2 ldmatrix per kk? need 8 n-tiles
                    // handled below
                }
                // 8 n-tiles -> 4 ldmatrix.x4 (each covers 2 n-tiles)
                #pragma unroll
                for (int j = 0; j < 4; j++) {
                    uint32_t bt[4];
                    int nrow = koff + (2 * j + (i8 >> 1)) * 8 + r8;
                    int kcc  = kk * 16 + (i8 & 1) * 8;
                    ldsm4(bt, kbase + (uint32_t)(nrow * FQ_STRIDE + kcc) * 2u);
                    mma16(sacc[2 * j],     qf[kk], bt[0], bt[1]);
                    mma16(sacc[2 * j + 1], qf[kk], bt[2], bt[3]);
                }
                (void)bf;
            }

            float mx0 = -1e30f, mx1 = -1e30f;
            #pragma unroll
            for (int nt = 0; nt < 8; nt++) {
                mx0 = fmaxf(mx0, fmaxf(sacc[nt][0], sacc[nt][1]));
                mx1 = fmaxf(mx1, fmaxf(sacc[nt][2], sacc[nt][3]));
            }
            mx0 = fmaxf(mx0, __shfl_xor_sync(0xffffffffu, mx0, 1));
            mx0 = fmaxf(mx0, __shfl_xor_sync(0xffffffffu, mx0, 2));
            mx1 = fmaxf(mx1, __shfl_xor_sync(0xffffffffu, mx1, 1));
            mx1 = fmaxf(mx1, __shfl_xor_sync(0xffffffffu, mx1, 2));

            float mnew0 = fmaxf(m_i[0], mx0);
            float mnew1 = fmaxf(m_i[1], mx1);
            float f0 = exp2f(m_i[0] - mnew0);
            float f1 = exp2f(m_i[1] - mnew1);
            m_i[0] = mnew0; m_i[1] = mnew1;
            l_i[0] *= f0;   l_i[1] *= f1;
            #pragma unroll
            for (int nt = 0; nt < 8; nt++) {
                oacc[nt][0] *= f0; oacc[nt][1] *= f0;
                oacc[nt][2] *= f1; oacc[nt][3] *= f1;
            }

            float rs0 = 0.f, rs1 = 0.f;
            #pragma unroll
            for (int nt = 0; nt < 8; nt++) {
                float p0 = exp2f(sacc[nt][0] - mnew0);
                float p1 = exp2f(sacc[nt][1] - mnew0);
                float p2 = exp2f(sacc[nt][2] - mnew1);
                float p3 = exp2f(sacc[nt][3] - mnew1);
                rs0 += p0 + p1; rs1 += p2 + p3;
                *(__half2*)&Pw[gid * FP_STRIDE + nt * 8 + qid * 2] = __floats2half2_rn(p0, p1);
                *(__half2*)&Pw[(gid + 8) * FP_STRIDE + nt * 8 + qid * 2] = __floats2half2_rn(p2, p3);
            }
            rs0 += __shfl_xor_sync(0xffffffffu, rs0, 1);
            rs0 += __shfl_xor_sync(0xffffffffu, rs0, 2);
            rs1 += __shfl_xor_sync(0xffffffffu, rs1, 1);
            rs1 += __shfl_xor_sync(0xffffffffu, rs1, 2);
            l_i[0] += rs0; l_i[1] += rs1;

            __syncwarp();

            // O += P(16x64) @ V[koff:koff+64, :]
            #pragma unroll
            for (int kk2 = 0; kk2 < 4; kk2++) {
                uint32_t ap[4];
                {
                    int prow = (i8 & 1) * 8 + r8;
                    int pkc  = kk2 * 16 + (i8 >> 1) * 8;
                    ldsm4(ap, pbase + (uint32_t)(prow * FP_STRIDE + pkc) * 2u);
                }
                #pragma unroll
                for (int ntp = 0; ntp < 4; ntp++) {
                    int vrow = koff + kk2 * 16 + (t4 & 1) * 8 + r8;
                    int vcol = ntp * 16 + (t4 >> 1) * 8;
                    uint32_t addr = vbase + (uint32_t)(vrow * FQ_STRIDE + vcol) * 2u;
                    uint32_t r0, r1, r2, r3;
                    asm volatile(
                        "ldmatrix.sync.aligned.m8n8.x4.trans.shared.b16 {%0,%1,%2,%3}, [%4];"
                        : "=r"(r0), "=r"(r1), "=r"(r2), "=r"(r3) : "r"(addr));
                    mma16(oacc[2 * ntp],     ap, r0, r1);
                    mma16(oacc[2 * ntp + 1], ap, r2, r3);
                }
            }
            __syncwarp();
        }
    }

    float inv0 = 1.f / l_i[0];
    float inv1 = 1.f / l_i[1];
    __half2* C = (__half2*)(olin + (size_t)b * SEQ * DIM + h * HD);
    int row = m0 + warp * 16 + gid;
    #pragma unroll
    for (int nt = 0; nt < 8; nt++) {
        int col = nt * 8 + qid * 2;
        C[((size_t)row * DIM + col) >> 1] =
            __floats2half2_rn(oacc[nt][0] * inv0, oacc[nt][1] * inv0);
        C[((size_t)(row + 8) * DIM + col) >> 1] =
            __floats2half2_rn(oacc[nt][2] * inv1, oacc[nt][3] * inv1);
    }
}

// ---------------- launch ----------------
extern "C" void kernel_launch(void* const* d_in, const int* in_sizes, int n_in,
                              void* d_out, int out_size) {
    const float* x       = (const float*)d_in[0];
    const float* n1g     = (const float*)d_in[1];
    const float* n1b     = (const float*)d_in[2];
    const float* qkv_w   = (const float*)d_in[3];
    const float* qkv_b   = (const float*)d_in[4];
    const float* proj_w  = (const float*)d_in[5];
    const float* proj_b  = (const float*)d_in[6];
    const float* n2g     = (const float*)d_in[7];
    const float* n2b     = (const float*)d_in[8];
    const float* fc1_w   = (const float*)d_in[9];
    const float* fc1_b   = (const float*)d_in[10];
    const float* fc2_w   = (const float*)d_in[11];
    const float* fc2_b   = (const float*)d_in[12];
    float* out = (float*)d_out;

    __half *h1h, *h2h, *olinh, *h3h, *qkvh, *qkvwh, *projwh, *fc1wh, *fc2wh;
    float *x2;
    cudaGetSymbolAddress((void**)&h1h,    g_h1h);
    cudaGetSymbolAddress((void**)&h2h,    g_h2h);
    cudaGetSymbolAddress((void**)&olinh,  g_olinh);
    cudaGetSymbolAddress((void**)&h3h,    g_h3h);
    cudaGetSymbolAddress((void**)&qkvh,   g_qkvh);
    cudaGetSymbolAddress((void**)&x2,     g_x2);
    cudaGetSymbolAddress((void**)&qkvwh,  g_qkvwh);
    cudaGetSymbolAddress((void**)&projwh, g_projwh);
    cudaGetSymbolAddress((void**)&fc1wh,  g_fc1wh);
    cudaGetSymbolAddress((void**)&fc2wh,  g_fc2wh);

    cudaFuncSetAttribute(hgemm_tn_kernel<EPI_BIAS, 1>,
                         cudaFuncAttributeMaxDynamicSharedMemorySize, GEMM_SMEM);
    cudaFuncSetAttribute(hgemm_tn_kernel<EPI_BIAS_RES, 0>,
                         cudaFuncAttributeMaxDynamicSharedMemorySize, GEMM_SMEM);
    cudaFuncSetAttribute(hgemm_tn_kernel<EPI_BIAS_GELU, 1>,
                         cudaFuncAttributeMaxDynamicSharedMemorySize, GEMM_SMEM);
    cudaFuncSetAttribute(flash_kernel,
                         cudaFuncAttributeMaxDynamicSharedMemorySize, FLASH_SMEM);

    // 0) all weights fp32 -> fp16, one launch
    const int n0 = QKVDIM*DIM/4, n1 = DIM*DIM/4, n2 = HIDDEN*DIM/4, n3 = DIM*HIDDEN/4;
    cvt_all<<<(n0+n1+n2+n3 + 255)/256, 256>>>(
        (const float4*)qkv_w,  (__half2*)qkvwh,  n0,
        (const float4*)proj_w, (__half2*)projwh, n1,
        (const float4*)fc1_w,  (__half2*)fc1wh,  n2,
        (const float4*)fc2_w,  (__half2*)fc2wh,  n3);

    // 1) LN1 -> fp16
    ln_kernel<<<TOK, 256>>>(x, n1g, n1b, h1h);
    // 2) QKV = h1 @ qkv_w^T + b  (fp16 out)
    hgemm_tn_kernel<EPI_BIAS, 1><<<dim3(QKVDIM/128, TOK/128), 256, GEMM_SMEM>>>(
        h1h, DIM, qkvwh, DIM, qkvh, QKVDIM, DIM, qkv_b, nullptr, 0);
    // 3) fused fp16 attention -> olin (fp16)
    flash_kernel<<<dim3(SEQ/128, NBH), 256, FLASH_SMEM>>>(qkvh, olinh);
    // 4) x2 = x + olin @ proj_w^T + b (fp32)
    hgemm_tn_kernel<EPI_BIAS_RES, 0><<<dim3(DIM/128, TOK/128), 256, GEMM_SMEM>>>(
        olinh, DIM, projwh, DIM, x2, DIM, DIM, proj_b, x, DIM);
    // 5) LN2 -> fp16
    ln_kernel<<<TOK, 256>>>(x2, n2g, n2b, h2h);
    // 6) h3 = gelu(h2 @ fc1_w^T + b) (fp16 out)
    hgemm_tn_kernel<EPI_BIAS_GELU, 1><<<dim3(HIDDEN/128, TOK/128), 256, GEMM_SMEM>>>(
        h2h, DIM, fc1wh, DIM, h3h, HIDDEN, DIM, fc1_b, nullptr, 0);
    // 7) out = x2 + h3 @ fc2_w^T + b (fp32)
    hgemm_tn_kernel<EPI_BIAS_RES, 0><<<dim3(DIM/128, TOK/128), 256, GEMM_SMEM>>>(
        h3h, HIDDEN, fc2wh, HIDDEN, out, DIM, HIDDEN, fc2_b, x2, DIM);
}

// round 13
// speedup vs baseline: 2.0754x; 1.0201x over previous
#include <cuda_runtime.h>
#include <cuda_fp16.h>
#include <math.h>
#include <stdint.h>

// Problem dims
#define DIM     768
#define HEADS   12
#define HD      64
#define HIDDEN  3072
#define SEQ     1024
#define BATCHN  8
#define TOK     (BATCHN*SEQ)   // 8192
#define QKVDIM  (3*DIM)        // 2304
#define NBH     (BATCHN*HEADS) // 96

// fp16 GEMM tiling
#define BKH      64
#define HSTRIDE  72
#define STAGE_H  (128 * HSTRIDE)
#define GEMM_SMEM (2 * 2 * STAGE_H * 2)    // 73728 B -> 2 CTAs/SM

// fp16 flash smem (halves): Q | K | V   (P lives in registers now)
#define FQ_STRIDE 72
#define FTILE_H   (128 * FQ_STRIDE)
#define FLASH_SMEM (3 * FTILE_H * 2)       // 55296 B -> 2 CTAs/SM

#define LOG2E 1.44269504088896f

// ---------------- scratch ----------------
__device__ __half g_h1h[TOK*DIM];
__device__ __half g_h2h[TOK*DIM];
__device__ __half g_olinh[TOK*DIM];
__device__ __half g_h3h[(size_t)TOK*HIDDEN];
__device__ __half g_qkvh[(size_t)TOK*QKVDIM];
__device__ float  g_x2[TOK*DIM];
__device__ __half g_qkvwh[QKVDIM*DIM];
__device__ __half g_projwh[DIM*DIM];
__device__ __half g_fc1wh[HIDDEN*DIM];
__device__ __half g_fc2wh[DIM*HIDDEN];

// ---------------- helpers ----------------
__device__ __forceinline__ void mma16(float* d, const uint32_t* a, uint32_t b0, uint32_t b1) {
    asm volatile(
        "mma.sync.aligned.m16n8k16.row.col.f32.f16.f16.f32 "
        "{%0,%1,%2,%3}, {%4,%5,%6,%7}, {%8,%9}, {%0,%1,%2,%3};"
        : "+f"(d[0]), "+f"(d[1]), "+f"(d[2]), "+f"(d[3])
        : "r"(a[0]), "r"(a[1]), "r"(a[2]), "r"(a[3]), "r"(b0), "r"(b1));
}
__device__ __forceinline__ void ldsm4(uint32_t* r, uint32_t addr) {
    asm volatile("ldmatrix.sync.aligned.m8n8.x4.shared.b16 {%0,%1,%2,%3}, [%4];"
        : "=r"(r[0]), "=r"(r[1]), "=r"(r[2]), "=r"(r[3]) : "r"(addr));
}
__device__ __forceinline__ float gelu1(float x) {
    return 0.5f * x * (1.f + erff(x * 0.70710678118654752f));
}
__device__ __forceinline__ void cp16h(__half* dst, const __half* src) {
    unsigned d = (unsigned)__cvta_generic_to_shared(dst);
    asm volatile("cp.async.cg.shared.global [%0], [%1], 16;\n" :: "r"(d), "l"(src));
}
__device__ __forceinline__ void cp_commit() {
    asm volatile("cp.async.commit_group;\n");
}
template<int N>
__device__ __forceinline__ void cp_wait() {
    asm volatile("cp.async.wait_group %0;\n" :: "n"(N));
}

// ---------------- fused fp32 -> fp16 converter ----------------
__global__ void cvt_all(const float4* __restrict__ s0, __half2* __restrict__ d0, int n0,
                        const float4* __restrict__ s1, __half2* __restrict__ d1, int n1,
                        const float4* __restrict__ s2, __half2* __restrict__ d2, int n2,
                        const float4* __restrict__ s3, __half2* __restrict__ d3, int n3) {
    int i = blockIdx.x * blockDim.x + threadIdx.x;
    const float4* s; __half2* d;
    if (i < n0) { s = s0; d = d0; }
    else if ((i -= n0) < n1) { s = s1; d = d1; }
    else if ((i -= n1) < n2) { s = s2; d = d2; }
    else if ((i -= n2) < n3) { s = s3; d = d3; }
    else return;
    float4 v = s[i];
    d[2*i]   = __floats2half2_rn(v.x, v.y);
    d[2*i+1] = __floats2half2_rn(v.z, v.w);
}

// ---------------- LayerNorm (fp32 in, fp16 out) ----------------
__global__ void ln_kernel(const float* __restrict__ in,
                          const float* __restrict__ gam,
                          const float* __restrict__ bet,
                          __half* __restrict__ out) {
    int row = blockIdx.x;
    int t = threadIdx.x;
    const float* x = in + (size_t)row * DIM;
    float v0 = x[t], v1 = x[t + 256], v2 = x[t + 512];
    float s  = v0 + v1 + v2;
    float sq = v0*v0 + v1*v1 + v2*v2;
    __shared__ float redS[8], redQ[8];
    #pragma unroll
    for (int o = 16; o > 0; o >>= 1) {
        s  += __shfl_xor_sync(0xffffffffu, s,  o);
        sq += __shfl_xor_sync(0xffffffffu, sq, o);
    }
    if ((t & 31) == 0) { redS[t >> 5] = s; redQ[t >> 5] = sq; }
    __syncthreads();
    if (t < 32) {
        float s2 = (t < 8) ? redS[t] : 0.f;
        float q2 = (t < 8) ? redQ[t] : 0.f;
        #pragma unroll
        for (int o = 4; o > 0; o >>= 1) {
            s2 += __shfl_xor_sync(0xffffffffu, s2, o);
            q2 += __shfl_xor_sync(0xffffffffu, q2, o);
        }
        if (t == 0) { redS[0] = s2; redQ[0] = q2; }
    }
    __syncthreads();
    float mu  = redS[0] * (1.0f / DIM);
    float var = redQ[0] * (1.0f / DIM) - mu * mu;
    float inv = rsqrtf(var + 1e-5f);
    __half* o = out + (size_t)row * DIM;
    o[t]       = __float2half((v0 - mu) * inv * gam[t]       + bet[t]);
    o[t + 256] = __float2half((v1 - mu) * inv * gam[t + 256] + bet[t + 256]);
    o[t + 512] = __float2half((v2 - mu) * inv * gam[t + 512] + bet[t + 512]);
}

// ---------------- FP16 MMA GEMM (TN): unchanged from R12 ----------------
enum { EPI_BIAS = 1, EPI_BIAS_RES = 2, EPI_BIAS_GELU = 3 };

template<int EPI, int OUTH>
__global__ __launch_bounds__(256, 2)
void hgemm_tn_kernel(const __half* __restrict__ A, int lda,
                     const __half* __restrict__ W, int ldw,
                     void* __restrict__ Cv, int ldc, int K,
                     const float* __restrict__ bias,
                     const float* __restrict__ res, int ldres) {
    extern __shared__ __half smh[];
    const uint32_t smbase = (uint32_t)__cvta_generic_to_shared(smh);
    const int m0 = blockIdx.y * 128, n0 = blockIdx.x * 128;
    const int tid  = threadIdx.x;
    const int lane = tid & 31;
    const int warp = tid >> 5;
    const int m0w  = (warp >> 2) * 64;
    const int n0w  = (warp & 3) * 32;
    const int gid  = lane >> 2;
    const int qid  = lane & 3;
    const int i8   = lane >> 3;
    const int r8   = lane & 7;

    const int crow0 = tid >> 3;
    const int cgr   = tid & 7;

    float acc[4][4][4];
    #pragma unroll
    for (int i = 0; i < 4; i++)
        #pragma unroll
        for (int j = 0; j < 4; j++)
            #pragma unroll
            for (int r = 0; r < 4; r++) acc[i][j][r] = 0.f;

    const int nch = K / BKH;

    auto load_chunk = [&](int j) {
        __half* as = smh + (j & 1) * 2 * STAGE_H;
        __half* ws = as + STAGE_H;
        const __half* Aj = A + (size_t)m0 * lda + j * BKH + cgr * 8;
        const __half* Wj = W + (size_t)n0 * ldw + j * BKH + cgr * 8;
        #pragma unroll
        for (int r = 0; r < 4; r++) {
            int row = crow0 + r * 32;
            cp16h(&as[row * HSTRIDE + cgr * 8], Aj + (size_t)row * lda);
            cp16h(&ws[row * HSTRIDE + cgr * 8], Wj + (size_t)row * ldw);
        }
    };

    load_chunk(0);
    cp_commit();

    for (int i = 0; i < nch; i++) {
        cp_wait<0>();
        __syncthreads();

        if (i + 1 < nch) {
            load_chunk(i + 1);
            cp_commit();
        }

        const uint32_t abase = smbase + ((i & 1) * 2 * STAGE_H) * 2;
        const uint32_t bbase = abase + STAGE_H * 2;
        #pragma unroll
        for (int ks = 0; ks < 4; ks++) {
            uint32_t af[4][4];
            #pragma unroll
            for (int mt = 0; mt < 4; mt++) {
                int row = m0w + mt * 16 + (i8 & 1) * 8 + r8;
                int kc  = ks * 16 + (i8 >> 1) * 8;
                ldsm4(af[mt], abase + (uint32_t)(row * HSTRIDE + kc) * 2u);
            }
            uint32_t bf[8];
            #pragma unroll
            for (int j = 0; j < 2; j++) {
                int nrow = n0w + (2 * j + (i8 >> 1)) * 8 + r8;
                int kc   = ks * 16 + (i8 & 1) * 8;
                ldsm4(&bf[4 * j], bbase + (uint32_t)(nrow * HSTRIDE + kc) * 2u);
            }
            #pragma unroll
            for (int nt = 0; nt < 4; nt++)
                #pragma unroll
                for (int mt = 0; mt < 4; mt++)
                    mma16(acc[mt][nt], af[mt], bf[nt * 2], bf[nt * 2 + 1]);
        }
    }

    #pragma unroll
    for (int mt = 0; mt < 4; mt++) {
        #pragma unroll
        for (int nt = 0; nt < 4; nt++) {
            int row = m0 + m0w + mt * 16 + gid;
            int col = n0 + n0w + nt * 8 + qid * 2;
            float2 v0, v1;
            v0.x = acc[mt][nt][0]; v0.y = acc[mt][nt][1];
            v1.x = acc[mt][nt][2]; v1.y = acc[mt][nt][3];
            {
                float2 bb = *(const float2*)(bias + col);
                v0.x += bb.x; v0.y += bb.y; v1.x += bb.x; v1.y += bb.y;
            }
            if (EPI == EPI_BIAS_RES) {
                float2 r0 = *(const float2*)(res + (size_t)row * ldres + col);
                float2 r1 = *(const float2*)(res + (size_t)(row + 8) * ldres + col);
                v0.x += r0.x; v0.y += r0.y; v1.x += r1.x; v1.y += r1.y;
            }
            if (EPI == EPI_BIAS_GELU) {
                v0.x = gelu1(v0.x); v0.y = gelu1(v0.y);
                v1.x = gelu1(v1.x); v1.y = gelu1(v1.y);
            }
            if (OUTH) {
                __half2* C = (__half2*)Cv;
                C[((size_t)row * ldc + col) >> 1]       = __floats2half2_rn(v0.x, v0.y);
                C[((size_t)(row + 8) * ldc + col) >> 1] = __floats2half2_rn(v1.x, v1.y);
            } else {
                float* C = (float*)Cv;
                *(float2*)(C + (size_t)row * ldc + col) = v0;
                *(float2*)(C + (size_t)(row + 8) * ldc + col) = v1;
            }
        }
    }
}

// ---------------- FP16 flash attention: P kept in registers (FA2 repack) ----------
__global__ __launch_bounds__(256, 2)
void flash_kernel(const __half* __restrict__ qkv, __half* __restrict__ olin) {
    extern __shared__ __half smf[];
    __half* Qs = smf;
    __half* Ks = Qs + FTILE_H;
    __half* Vs = Ks + FTILE_H;

    const int bh = blockIdx.y;
    const int b = bh / HEADS, h = bh % HEADS;
    const int m0 = blockIdx.x * 128;
    const __half* Qg = qkv + (size_t)b * SEQ * QKVDIM + h * HD;
    const __half* Kg = Qg + DIM;
    const __half* Vg = Qg + 2 * DIM;

    const int tid = threadIdx.x, lane = tid & 31, warp = tid >> 5;
    const int gid = lane >> 2, qid = lane & 3;
    const int i8 = lane >> 3, r8 = lane & 7;
    const int t4 = lane >> 3;

    const uint32_t qbase = (uint32_t)__cvta_generic_to_shared(Qs);
    const uint32_t kbase = (uint32_t)__cvta_generic_to_shared(Ks);
    const uint32_t vbase = (uint32_t)__cvta_generic_to_shared(Vs);

    // Q tile
    #pragma unroll
    for (int i = 0; i < 4; i++) {
        int f = i * 256 + tid;
        int r = f >> 3, c8 = (f & 7) * 8;
        cp16h(&Qs[r * FQ_STRIDE + c8], Qg + (size_t)(m0 + r) * QKVDIM + c8);
    }
    cp_commit();
    cp_wait<0>();
    __syncthreads();

    // preload Q fragments via ldmatrix, pre-scaled by 0.125*log2e
    const __half2 kscale = __floats2half2_rn(0.125f * LOG2E, 0.125f * LOG2E);
    uint32_t qf[4][4];
    #pragma unroll
    for (int kk = 0; kk < 4; kk++) {
        int row = warp * 16 + (i8 & 1) * 8 + r8;
        int kc  = kk * 16 + (i8 >> 1) * 8;
        ldsm4(qf[kk], qbase + (uint32_t)(row * FQ_STRIDE + kc) * 2u);
        #pragma unroll
        for (int r = 0; r < 4; r++) {
            __half2 t = __hmul2(*(__half2*)&qf[kk][r], kscale);
            qf[kk][r] = *(uint32_t*)&t;
        }
    }

    float m_i[2] = {-1e30f, -1e30f};
    float l_i[2] = {0.f, 0.f};
    float oacc[8][4];
    #pragma unroll
    for (int nt = 0; nt < 8; nt++)
        #pragma unroll
        for (int r = 0; r < 4; r++) oacc[nt][r] = 0.f;

    for (int kc = 0; kc < 8; kc++) {
        __syncthreads();
        const __half* Kc = Kg + (size_t)(kc * 128) * QKVDIM;
        const __half* Vc = Vg + (size_t)(kc * 128) * QKVDIM;
        #pragma unroll
        for (int i = 0; i < 4; i++) {
            int f = i * 256 + tid;
            int r = f >> 3, c8 = (f & 7) * 8;
            cp16h(&Ks[r * FQ_STRIDE + c8], Kc + (size_t)r * QKVDIM + c8);
            cp16h(&Vs[r * FQ_STRIDE + c8], Vc + (size_t)r * QKVDIM + c8);
        }
        cp_commit();
        cp_wait<0>();
        __syncthreads();

        // two 64-key halves with online softmax
        #pragma unroll
        for (int half = 0; half < 2; half++) {
            const int koff = half * 64;

            float sacc[8][4];
            #pragma unroll
            for (int nt = 0; nt < 8; nt++)
                #pragma unroll
                for (int r = 0; r < 4; r++) sacc[nt][r] = 0.f;
            #pragma unroll
            for (int kk = 0; kk < 4; kk++) {
                #pragma unroll
                for (int j = 0; j < 4; j++) {
                    uint32_t bt[4];
                    int nrow = koff + (2 * j + (i8 >> 1)) * 8 + r8;
                    int kcc  = kk * 16 + (i8 & 1) * 8;
                    ldsm4(bt, kbase + (uint32_t)(nrow * FQ_STRIDE + kcc) * 2u);
                    mma16(sacc[2 * j],     qf[kk], bt[0], bt[1]);
                    mma16(sacc[2 * j + 1], qf[kk], bt[2], bt[3]);
                }
            }

            float mx0 = -1e30f, mx1 = -1e30f;
            #pragma unroll
            for (int nt = 0; nt < 8; nt++) {
                mx0 = fmaxf(mx0, fmaxf(sacc[nt][0], sacc[nt][1]));
                mx1 = fmaxf(mx1, fmaxf(sacc[nt][2], sacc[nt][3]));
            }
            mx0 = fmaxf(mx0, __shfl_xor_sync(0xffffffffu, mx0, 1));
            mx0 = fmaxf(mx0, __shfl_xor_sync(0xffffffffu, mx0, 2));
            mx1 = fmaxf(mx1, __shfl_xor_sync(0xffffffffu, mx1, 1));
            mx1 = fmaxf(mx1, __shfl_xor_sync(0xffffffffu, mx1, 2));

            float mnew0 = fmaxf(m_i[0], mx0);
            float mnew1 = fmaxf(m_i[1], mx1);
            float f0 = exp2f(m_i[0] - mnew0);
            float f1 = exp2f(m_i[1] - mnew1);
            m_i[0] = mnew0; m_i[1] = mnew1;
            l_i[0] *= f0;   l_i[1] *= f1;
            #pragma unroll
            for (int nt = 0; nt < 8; nt++) {
                oacc[nt][0] *= f0; oacc[nt][1] *= f0;
                oacc[nt][2] *= f1; oacc[nt][3] *= f1;
            }

            // P = exp2(S - m): pack directly into PV A-fragments (registers only)
            float rs0 = 0.f, rs1 = 0.f;
            uint32_t ph[8][2];
            #pragma unroll
            for (int nt = 0; nt < 8; nt++) {
                float p0 = exp2f(sacc[nt][0] - mnew0);
                float p1 = exp2f(sacc[nt][1] - mnew0);
                float p2 = exp2f(sacc[nt][2] - mnew1);
                float p3 = exp2f(sacc[nt][3] - mnew1);
                rs0 += p0 + p1; rs1 += p2 + p3;
                __half2 lo = __floats2half2_rn(p0, p1);
                __half2 hi = __floats2half2_rn(p2, p3);
                ph[nt][0] = *(uint32_t*)&lo;
                ph[nt][1] = *(uint32_t*)&hi;
            }
            rs0 += __shfl_xor_sync(0xffffffffu, rs0, 1);
            rs0 += __shfl_xor_sync(0xffffffffu, rs0, 2);
            rs1 += __shfl_xor_sync(0xffffffffu, rs1, 1);
            rs1 += __shfl_xor_sync(0xffffffffu, rs1, 2);
            l_i[0] += rs0; l_i[1] += rs1;

            // O += P(16x64) @ V[koff:koff+64, :] — A frags from ph, no smem
            #pragma unroll
            for (int kk2 = 0; kk2 < 4; kk2++) {
                uint32_t ap[4];
                ap[0] = ph[2 * kk2][0];
                ap[1] = ph[2 * kk2][1];
                ap[2] = ph[2 * kk2 + 1][0];
                ap[3] = ph[2 * kk2 + 1][1];
                #pragma unroll
                for (int ntp = 0; ntp < 4; ntp++) {
                    int vrow = koff + kk2 * 16 + (t4 & 1) * 8 + r8;
                    int vcol = ntp * 16 + (t4 >> 1) * 8;
                    uint32_t addr = vbase + (uint32_t)(vrow * FQ_STRIDE + vcol) * 2u;
                    uint32_t r0, r1, r2, r3;
                    asm volatile(
                        "ldmatrix.sync.aligned.m8n8.x4.trans.shared.b16 {%0,%1,%2,%3}, [%4];"
                        : "=r"(r0), "=r"(r1), "=r"(r2), "=r"(r3) : "r"(addr));
                    mma16(oacc[2 * ntp],     ap, r0, r1);
                    mma16(oacc[2 * ntp + 1], ap, r2, r3);
                }
            }
        }
    }

    float inv0 = 1.f / l_i[0];
    float inv1 = 1.f / l_i[1];
    __half2* C = (__half2*)(olin + (size_t)b * SEQ * DIM + h * HD);
    int row = m0 + warp * 16 + gid;
    #pragma unroll
    for (int nt = 0; nt < 8; nt++) {
        int col = nt * 8 + qid * 2;
        C[((size_t)row * DIM + col) >> 1] =
            __floats2half2_rn(oacc[nt][0] * inv0, oacc[nt][1] * inv0);
        C[((size_t)(row + 8) * DIM + col) >> 1] =
            __floats2half2_rn(oacc[nt][2] * inv1, oacc[nt][3] * inv1);
    }
}

// ---------------- launch ----------------
extern "C" void kernel_launch(void* const* d_in, const int* in_sizes, int n_in,
                              void* d_out, int out_size) {
    const float* x       = (const float*)d_in[0];
    const float* n1g     = (const float*)d_in[1];
    const float* n1b     = (const float*)d_in[2];
    const float* qkv_w   = (const float*)d_in[3];
    const float* qkv_b   = (const float*)d_in[4];
    const float* proj_w  = (const float*)d_in[5];
    const float* proj_b  = (const float*)d_in[6];
    const float* n2g     = (const float*)d_in[7];
    const float* n2b     = (const float*)d_in[8];
    const float* fc1_w   = (const float*)d_in[9];
    const float* fc1_b   = (const float*)d_in[10];
    const float* fc2_w   = (const float*)d_in[11];
    const float* fc2_b   = (const float*)d_in[12];
    float* out = (float*)d_out;

    __half *h1h, *h2h, *olinh, *h3h, *qkvh, *qkvwh, *projwh, *fc1wh, *fc2wh;
    float *x2;
    cudaGetSymbolAddress((void**)&h1h,    g_h1h);
    cudaGetSymbolAddress((void**)&h2h,    g_h2h);
    cudaGetSymbolAddress((void**)&olinh,  g_olinh);
    cudaGetSymbolAddress((void**)&h3h,    g_h3h);
    cudaGetSymbolAddress((void**)&qkvh,   g_qkvh);
    cudaGetSymbolAddress((void**)&x2,     g_x2);
    cudaGetSymbolAddress((void**)&qkvwh,  g_qkvwh);
    cudaGetSymbolAddress((void**)&projwh, g_projwh);
    cudaGetSymbolAddress((void**)&fc1wh,  g_fc1wh);
    cudaGetSymbolAddress((void**)&fc2wh,  g_fc2wh);

    cudaFuncSetAttribute(hgemm_tn_kernel<EPI_BIAS, 1>,
                         cudaFuncAttributeMaxDynamicSharedMemorySize, GEMM_SMEM);
    cudaFuncSetAttribute(hgemm_tn_kernel<EPI_BIAS_RES, 0>,
                         cudaFuncAttributeMaxDynamicSharedMemorySize, GEMM_SMEM);
    cudaFuncSetAttribute(hgemm_tn_kernel<EPI_BIAS_GELU, 1>,
                         cudaFuncAttributeMaxDynamicSharedMemorySize, GEMM_SMEM);
    cudaFuncSetAttribute(flash_kernel,
                         cudaFuncAttributeMaxDynamicSharedMemorySize, FLASH_SMEM);

    // 0) all weights fp32 -> fp16, one launch
    const int n0 = QKVDIM*DIM/4, n1 = DIM*DIM/4, n2 = HIDDEN*DIM/4, n3 = DIM*HIDDEN/4;
    cvt_all<<<(n0+n1+n2+n3 + 255)/256, 256>>>(
        (const float4*)qkv_w,  (__half2*)qkvwh,  n0,
        (const float4*)proj_w, (__half2*)projwh, n1,
        (const float4*)fc1_w,  (__half2*)fc1wh,  n2,
        (const float4*)fc2_w,  (__half2*)fc2wh,  n3);

    // 1) LN1 -> fp16
    ln_kernel<<<TOK, 256>>>(x, n1g, n1b, h1h);
    // 2) QKV = h1 @ qkv_w^T + b  (fp16 out)
    hgemm_tn_kernel<EPI_BIAS, 1><<<dim3(QKVDIM/128, TOK/128), 256, GEMM_SMEM>>>(
        h1h, DIM, qkvwh, DIM, qkvh, QKVDIM, DIM, qkv_b, nullptr, 0);
    // 3) fused fp16 attention -> olin (fp16)
    flash_kernel<<<dim3(SEQ/128, NBH), 256, FLASH_SMEM>>>(qkvh, olinh);
    // 4) x2 = x + olin @ proj_w^T + b (fp32)
    hgemm_tn_kernel<EPI_BIAS_RES, 0><<<dim3(DIM/128, TOK/128), 256, GEMM_SMEM>>>(
        olinh, DIM, projwh, DIM, x2, DIM, DIM, proj_b, x, DIM);
    // 5) LN2 -> fp16
    ln_kernel<<<TOK, 256>>>(x2, n2g, n2b, h2h);
    // 6) h3 = gelu(h2 @ fc1_w^T + b) (fp16 out)
    hgemm_tn_kernel<EPI_BIAS_GELU, 1><<<dim3(HIDDEN/128, TOK/128), 256, GEMM_SMEM>>>(
        h2h, DIM, fc1wh, DIM, h3h, HIDDEN, DIM, fc1_b, nullptr, 0);
    // 7) out = x2 + h3 @ fc2_w^T + b (fp32)
    hgemm_tn_kernel<EPI_BIAS_RES, 0><<<dim3(DIM/128, TOK/128), 256, GEMM_SMEM>>>(
        h3h, HIDDEN, fc2wh, HIDDEN, out, DIM, HIDDEN, fc2_b, x2, DIM);
}

// round 14
// speedup vs baseline: 2.1136x; 1.0184x over previous
#include <cuda_runtime.h>
#include <cuda_fp16.h>
#include <math.h>
#include <stdint.h>

// Problem dims
#define DIM     768
#define HEADS   12
#define HD      64
#define HIDDEN  3072
#define SEQ     1024
#define BATCHN  8
#define TOK     (BATCHN*SEQ)   // 8192
#define QKVDIM  (3*DIM)        // 2304
#define NBH     (BATCHN*HEADS) // 96

// fp16 GEMM tiling: 3-stage cp.async ring
#define BKH      64
#define HSTRIDE  72
#define STAGE_H  (128 * HSTRIDE)
#define GEMM_SMEM (3 * 2 * STAGE_H * 2)    // 110592 B -> 2 CTAs/SM (221KB/SM)

// fp16 flash smem (halves): Q | KV0(K,V) | KV1(K,V)
#define FQ_STRIDE 72
#define FTILE_H   (128 * FQ_STRIDE)
#define FLASH_SMEM (5 * FTILE_H * 2)       // 92160 B -> 2 CTAs/SM (180KB/SM)

#define LOG2E 1.44269504088896f

// ---------------- scratch ----------------
__device__ __half g_h1h[TOK*DIM];
__device__ __half g_h2h[TOK*DIM];
__device__ __half g_olinh[TOK*DIM];
__device__ __half g_h3h[(size_t)TOK*HIDDEN];
__device__ __half g_qkvh[(size_t)TOK*QKVDIM];
__device__ float  g_x2[TOK*DIM];
__device__ __half g_qkvwh[QKVDIM*DIM];
__device__ __half g_projwh[DIM*DIM];
__device__ __half g_fc1wh[HIDDEN*DIM];
__device__ __half g_fc2wh[DIM*HIDDEN];

// ---------------- helpers ----------------
__device__ __forceinline__ void mma16(float* d, const uint32_t* a, uint32_t b0, uint32_t b1) {
    asm volatile(
        "mma.sync.aligned.m16n8k16.row.col.f32.f16.f16.f32 "
        "{%0,%1,%2,%3}, {%4,%5,%6,%7}, {%8,%9}, {%0,%1,%2,%3};"
        : "+f"(d[0]), "+f"(d[1]), "+f"(d[2]), "+f"(d[3])
        : "r"(a[0]), "r"(a[1]), "r"(a[2]), "r"(a[3]), "r"(b0), "r"(b1));
}
__device__ __forceinline__ void ldsm4(uint32_t* r, uint32_t addr) {
    asm volatile("ldmatrix.sync.aligned.m8n8.x4.shared.b16 {%0,%1,%2,%3}, [%4];"
        : "=r"(r[0]), "=r"(r[1]), "=r"(r[2]), "=r"(r[3]) : "r"(addr));
}
__device__ __forceinline__ float gelu1(float x) {
    return 0.5f * x * (1.f + erff(x * 0.70710678118654752f));
}
__device__ __forceinline__ void cp16h(__half* dst, const __half* src) {
    unsigned d = (unsigned)__cvta_generic_to_shared(dst);
    asm volatile("cp.async.cg.shared.global [%0], [%1], 16;\n" :: "r"(d), "l"(src));
}
__device__ __forceinline__ void cp_commit() {
    asm volatile("cp.async.commit_group;\n");
}
template<int N>
__device__ __forceinline__ void cp_wait() {
    asm volatile("cp.async.wait_group %0;\n" :: "n"(N));
}

// ---------------- fused fp32 -> fp16 converter ----------------
__global__ void cvt_all(const float4* __restrict__ s0, __half2* __restrict__ d0, int n0,
                        const float4* __restrict__ s1, __half2* __restrict__ d1, int n1,
                        const float4* __restrict__ s2, __half2* __restrict__ d2, int n2,
                        const float4* __restrict__ s3, __half2* __restrict__ d3, int n3) {
    int i = blockIdx.x * blockDim.x + threadIdx.x;
    const float4* s; __half2* d;
    if (i < n0) { s = s0; d = d0; }
    else if ((i -= n0) < n1) { s = s1; d = d1; }
    else if ((i -= n1) < n2) { s = s2; d = d2; }
    else if ((i -= n2) < n3) { s = s3; d = d3; }
    else return;
    float4 v = s[i];
    d[2*i]   = __floats2half2_rn(v.x, v.y);
    d[2*i+1] = __floats2half2_rn(v.z, v.w);
}

// ---------------- LayerNorm (fp32 in, fp16 out) ----------------
__global__ void ln_kernel(const float* __restrict__ in,
                          const float* __restrict__ gam,
                          const float* __restrict__ bet,
                          __half* __restrict__ out) {
    int row = blockIdx.x;
    int t = threadIdx.x;
    const float* x = in + (size_t)row * DIM;
    float v0 = x[t], v1 = x[t + 256], v2 = x[t + 512];
    float s  = v0 + v1 + v2;
    float sq = v0*v0 + v1*v1 + v2*v2;
    __shared__ float redS[8], redQ[8];
    #pragma unroll
    for (int o = 16; o > 0; o >>= 1) {
        s  += __shfl_xor_sync(0xffffffffu, s,  o);
        sq += __shfl_xor_sync(0xffffffffu, sq, o);
    }
    if ((t & 31) == 0) { redS[t >> 5] = s; redQ[t >> 5] = sq; }
    __syncthreads();
    if (t < 32) {
        float s2 = (t < 8) ? redS[t] : 0.f;
        float q2 = (t < 8) ? redQ[t] : 0.f;
        #pragma unroll
        for (int o = 4; o > 0; o >>= 1) {
            s2 += __shfl_xor_sync(0xffffffffu, s2, o);
            q2 += __shfl_xor_sync(0xffffffffu, q2, o);
        }
        if (t == 0) { redS[0] = s2; redQ[0] = q2; }
    }
    __syncthreads();
    float mu  = redS[0] * (1.0f / DIM);
    float var = redQ[0] * (1.0f / DIM) - mu * mu;
    float inv = rsqrtf(var + 1e-5f);
    __half* o = out + (size_t)row * DIM;
    o[t]       = __float2half((v0 - mu) * inv * gam[t]       + bet[t]);
    o[t + 256] = __float2half((v1 - mu) * inv * gam[t + 256] + bet[t + 256]);
    o[t + 512] = __float2half((v2 - mu) * inv * gam[t + 512] + bet[t + 512]);
}

// ---------------- FP16 MMA GEMM (TN): 3-stage ring, distance-2 prefetch ----------
enum { EPI_BIAS = 1, EPI_BIAS_RES = 2, EPI_BIAS_GELU = 3 };

template<int EPI, int OUTH>
__global__ __launch_bounds__(256, 2)
void hgemm_tn_kernel(const __half* __restrict__ A, int lda,
                     const __half* __restrict__ W, int ldw,
                     void* __restrict__ Cv, int ldc, int K,
                     const float* __restrict__ bias,
                     const float* __restrict__ res, int ldres) {
    extern __shared__ __half smh[];
    const uint32_t smbase = (uint32_t)__cvta_generic_to_shared(smh);
    const int m0 = blockIdx.y * 128, n0 = blockIdx.x * 128;
    const int tid  = threadIdx.x;
    const int lane = tid & 31;
    const int warp = tid >> 5;
    const int m0w  = (warp >> 2) * 64;
    const int n0w  = (warp & 3) * 32;
    const int gid  = lane >> 2;
    const int qid  = lane & 3;
    const int i8   = lane >> 3;
    const int r8   = lane & 7;

    const int crow0 = tid >> 3;
    const int cgr   = tid & 7;

    float acc[4][4][4];
    #pragma unroll
    for (int i = 0; i < 4; i++)
        #pragma unroll
        for (int j = 0; j < 4; j++)
            #pragma unroll
            for (int r = 0; r < 4; r++) acc[i][j][r] = 0.f;

    const int nch = K / BKH;

    auto load_chunk = [&](int j) {
        __half* as = smh + (j % 3) * 2 * STAGE_H;
        __half* ws = as + STAGE_H;
        const __half* Aj = A + (size_t)m0 * lda + j * BKH + cgr * 8;
        const __half* Wj = W + (size_t)n0 * ldw + j * BKH + cgr * 8;
        #pragma unroll
        for (int r = 0; r < 4; r++) {
            int row = crow0 + r * 32;
            cp16h(&as[row * HSTRIDE + cgr * 8], Aj + (size_t)row * lda);
            cp16h(&ws[row * HSTRIDE + cgr * 8], Wj + (size_t)row * ldw);
        }
    };

    load_chunk(0);
    cp_commit();
    load_chunk(1);
    cp_commit();

    for (int i = 0; i < nch; i++) {
        cp_wait<1>();          // chunk i landed; i+1 may still be in flight
        __syncthreads();

        if (i + 2 < nch) load_chunk(i + 2);
        cp_commit();           // unconditional: keep group accounting uniform

        const uint32_t abase = smbase + ((i % 3) * 2 * STAGE_H) * 2;
        const uint32_t bbase = abase + STAGE_H * 2;
        #pragma unroll
        for (int ks = 0; ks < 4; ks++) {
            uint32_t af[4][4];
            #pragma unroll
            for (int mt = 0; mt < 4; mt++) {
                int row = m0w + mt * 16 + (i8 & 1) * 8 + r8;
                int kc  = ks * 16 + (i8 >> 1) * 8;
                ldsm4(af[mt], abase + (uint32_t)(row * HSTRIDE + kc) * 2u);
            }
            uint32_t bf[8];
            #pragma unroll
            for (int j = 0; j < 2; j++) {
                int nrow = n0w + (2 * j + (i8 >> 1)) * 8 + r8;
                int kc   = ks * 16 + (i8 & 1) * 8;
                ldsm4(&bf[4 * j], bbase + (uint32_t)(nrow * HSTRIDE + kc) * 2u);
            }
            #pragma unroll
            for (int nt = 0; nt < 4; nt++)
                #pragma unroll
                for (int mt = 0; mt < 4; mt++)
                    mma16(acc[mt][nt], af[mt], bf[nt * 2], bf[nt * 2 + 1]);
        }
    }

    #pragma unroll
    for (int mt = 0; mt < 4; mt++) {
        #pragma unroll
        for (int nt = 0; nt < 4; nt++) {
            int row = m0 + m0w + mt * 16 + gid;
            int col = n0 + n0w + nt * 8 + qid * 2;
            float2 v0, v1;
            v0.x = acc[mt][nt][0]; v0.y = acc[mt][nt][1];
            v1.x = acc[mt][nt][2]; v1.y = acc[mt][nt][3];
            {
                float2 bb = *(const float2*)(bias + col);
                v0.x += bb.x; v0.y += bb.y; v1.x += bb.x; v1.y += bb.y;
            }
            if (EPI == EPI_BIAS_RES) {
                float2 r0 = *(const float2*)(res + (size_t)row * ldres + col);
                float2 r1 = *(const float2*)(res + (size_t)(row + 8) * ldres + col);
                v0.x += r0.x; v0.y += r0.y; v1.x += r1.x; v1.y += r1.y;
            }
            if (EPI == EPI_BIAS_GELU) {
                v0.x = gelu1(v0.x); v0.y = gelu1(v0.y);
                v1.x = gelu1(v1.x); v1.y = gelu1(v1.y);
            }
            if (OUTH) {
                __half2* C = (__half2*)Cv;
                C[((size_t)row * ldc + col) >> 1]       = __floats2half2_rn(v0.x, v0.y);
                C[((size_t)(row + 8) * ldc + col) >> 1] = __floats2half2_rn(v1.x, v1.y);
            } else {
                float* C = (float*)Cv;
                *(float2*)(C + (size_t)row * ldc + col) = v0;
                *(float2*)(C + (size_t)(row + 8) * ldc + col) = v1;
            }
        }
    }
}

// ---------------- FP16 flash attention: reg-P + double-buffered KV ----------------
__global__ __launch_bounds__(256, 2)
void flash_kernel(const __half* __restrict__ qkv, __half* __restrict__ olin) {
    extern __shared__ __half smf[];
    __half* Qs  = smf;
    __half* KV0 = Qs + FTILE_H;               // K at +0, V at +FTILE_H
    __half* KV1 = KV0 + 2 * FTILE_H;

    const int bh = blockIdx.y;
    const int b = bh / HEADS, h = bh % HEADS;
    const int m0 = blockIdx.x * 128;
    const __half* Qg = qkv + (size_t)b * SEQ * QKVDIM + h * HD;
    const __half* Kg = Qg + DIM;
    const __half* Vg = Qg + 2 * DIM;

    const int tid = threadIdx.x, lane = tid & 31, warp = tid >> 5;
    const int gid = lane >> 2, qid = lane & 3;
    const int i8 = lane >> 3, r8 = lane & 7;
    const int t4 = lane >> 3;

    const uint32_t qbase = (uint32_t)__cvta_generic_to_shared(Qs);

    auto load_kv = [&](int kc, __half* dst) {
        const __half* Kc = Kg + (size_t)(kc * 128) * QKVDIM;
        const __half* Vc = Vg + (size_t)(kc * 128) * QKVDIM;
        #pragma unroll
        for (int i = 0; i < 4; i++) {
            int f = i * 256 + tid;
            int r = f >> 3, c8 = (f & 7) * 8;
            cp16h(&dst[r * FQ_STRIDE + c8], Kc + (size_t)r * QKVDIM + c8);
            cp16h(&dst[FTILE_H + r * FQ_STRIDE + c8], Vc + (size_t)r * QKVDIM + c8);
        }
    };

    // group: Q tile
    #pragma unroll
    for (int i = 0; i < 4; i++) {
        int f = i * 256 + tid;
        int r = f >> 3, c8 = (f & 7) * 8;
        cp16h(&Qs[r * FQ_STRIDE + c8], Qg + (size_t)(m0 + r) * QKVDIM + c8);
    }
    cp_commit();
    // group: KV chunk 0
    load_kv(0, KV0);
    cp_commit();

    cp_wait<1>();          // Q landed
    __syncthreads();

    // preload Q fragments via ldmatrix, pre-scaled by 0.125*log2e
    const __half2 kscale = __floats2half2_rn(0.125f * LOG2E, 0.125f * LOG2E);
    uint32_t qf[4][4];
    #pragma unroll
    for (int kk = 0; kk < 4; kk++) {
        int row = warp * 16 + (i8 & 1) * 8 + r8;
        int kc  = kk * 16 + (i8 >> 1) * 8;
        ldsm4(qf[kk], qbase + (uint32_t)(row * FQ_STRIDE + kc) * 2u);
        #pragma unroll
        for (int r = 0; r < 4; r++) {
            __half2 t = __hmul2(*(__half2*)&qf[kk][r], kscale);
            qf[kk][r] = *(uint32_t*)&t;
        }
    }

    float m_i[2] = {-1e30f, -1e30f};
    float l_i[2] = {0.f, 0.f};
    float oacc[8][4];
    #pragma unroll
    for (int nt = 0; nt < 8; nt++)
        #pragma unroll
        for (int r = 0; r < 4; r++) oacc[nt][r] = 0.f;

    for (int kc = 0; kc < 8; kc++) {
        __half* cur = (kc & 1) ? KV1 : KV0;
        __half* nxt = (kc & 1) ? KV0 : KV1;

        // prefetch next chunk (buffer freed by end-of-previous-iteration sync)
        if (kc + 1 < 8) load_kv(kc + 1, nxt);
        cp_commit();
        cp_wait<1>();      // chunk kc landed; kc+1 still in flight
        __syncthreads();

        const uint32_t kbase = (uint32_t)__cvta_generic_to_shared(cur);
        const uint32_t vbase = kbase + (uint32_t)FTILE_H * 2u;

        // two 64-key halves with online softmax
        #pragma unroll
        for (int half = 0; half < 2; half++) {
            const int koff = half * 64;

            float sacc[8][4];
            #pragma unroll
            for (int nt = 0; nt < 8; nt++)
                #pragma unroll
                for (int r = 0; r < 4; r++) sacc[nt][r] = 0.f;
            #pragma unroll
            for (int kk = 0; kk < 4; kk++) {
                #pragma unroll
                for (int j = 0; j < 4; j++) {
                    uint32_t bt[4];
                    int nrow = koff + (2 * j + (i8 >> 1)) * 8 + r8;
                    int kcc  = kk * 16 + (i8 & 1) * 8;
                    ldsm4(bt, kbase + (uint32_t)(nrow * FQ_STRIDE + kcc) * 2u);
                    mma16(sacc[2 * j],     qf[kk], bt[0], bt[1]);
                    mma16(sacc[2 * j + 1], qf[kk], bt[2], bt[3]);
                }
            }

            float mx0 = -1e30f, mx1 = -1e30f;
            #pragma unroll
            for (int nt = 0; nt < 8; nt++) {
                mx0 = fmaxf(mx0, fmaxf(sacc[nt][0], sacc[nt][1]));
                mx1 = fmaxf(mx1, fmaxf(sacc[nt][2], sacc[nt][3]));
            }
            mx0 = fmaxf(mx0, __shfl_xor_sync(0xffffffffu, mx0, 1));
            mx0 = fmaxf(mx0, __shfl_xor_sync(0xffffffffu, mx0, 2));
            mx1 = fmaxf(mx1, __shfl_xor_sync(0xffffffffu, mx1, 1));
            mx1 = fmaxf(mx1, __shfl_xor_sync(0xffffffffu, mx1, 2));

            float mnew0 = fmaxf(m_i[0], mx0);
            float mnew1 = fmaxf(m_i[1], mx1);
            float f0 = exp2f(m_i[0] - mnew0);
            float f1 = exp2f(m_i[1] - mnew1);
            m_i[0] = mnew0; m_i[1] = mnew1;
            l_i[0] *= f0;   l_i[1] *= f1;
            #pragma unroll
            for (int nt = 0; nt < 8; nt++) {
                oacc[nt][0] *= f0; oacc[nt][1] *= f0;
                oacc[nt][2] *= f1; oacc[nt][3] *= f1;
            }

            // P = exp2(S - m): pack into PV A-fragments (registers only)
            float rs0 = 0.f, rs1 = 0.f;
            uint32_t ph[8][2];
            #pragma unroll
            for (int nt = 0; nt < 8; nt++) {
                float p0 = exp2f(sacc[nt][0] - mnew0);
                float p1 = exp2f(sacc[nt][1] - mnew0);
                float p2 = exp2f(sacc[nt][2] - mnew1);
                float p3 = exp2f(sacc[nt][3] - mnew1);
                rs0 += p0 + p1; rs1 += p2 + p3;
                __half2 lo = __floats2half2_rn(p0, p1);
                __half2 hi = __floats2half2_rn(p2, p3);
                ph[nt][0] = *(uint32_t*)&lo;
                ph[nt][1] = *(uint32_t*)&hi;
            }
            rs0 += __shfl_xor_sync(0xffffffffu, rs0, 1);
            rs0 += __shfl_xor_sync(0xffffffffu, rs0, 2);
            rs1 += __shfl_xor_sync(0xffffffffu, rs1, 1);
            rs1 += __shfl_xor_sync(0xffffffffu, rs1, 2);
            l_i[0] += rs0; l_i[1] += rs1;

            // O += P(16x64) @ V[koff:koff+64, :]
            #pragma unroll
            for (int kk2 = 0; kk2 < 4; kk2++) {
                uint32_t ap[4];
                ap[0] = ph[2 * kk2][0];
                ap[1] = ph[2 * kk2][1];
                ap[2] = ph[2 * kk2 + 1][0];
                ap[3] = ph[2 * kk2 + 1][1];
                #pragma unroll
                for (int ntp = 0; ntp < 4; ntp++) {
                    int vrow = koff + kk2 * 16 + (t4 & 1) * 8 + r8;
                    int vcol = ntp * 16 + (t4 >> 1) * 8;
                    uint32_t addr = vbase + (uint32_t)(vrow * FQ_STRIDE + vcol) * 2u;
                    uint32_t r0, r1, r2, r3;
                    asm volatile(
                        "ldmatrix.sync.aligned.m8n8.x4.trans.shared.b16 {%0,%1,%2,%3}, [%4];"
                        : "=r"(r0), "=r"(r1), "=r"(r2), "=r"(r3) : "r"(addr));
                    mma16(oacc[2 * ntp],     ap, r0, r1);
                    mma16(oacc[2 * ntp + 1], ap, r2, r3);
                }
            }
        }
        __syncthreads();   // all warps done reading cur before it is refilled
    }

    float inv0 = 1.f / l_i[0];
    float inv1 = 1.f / l_i[1];
    __half2* C = (__half2*)(olin + (size_t)b * SEQ * DIM + h * HD);
    int row = m0 + warp * 16 + gid;
    #pragma unroll
    for (int nt = 0; nt < 8; nt++) {
        int col = nt * 8 + qid * 2;
        C[((size_t)row * DIM + col) >> 1] =
            __floats2half2_rn(oacc[nt][0] * inv0, oacc[nt][1] * inv0);
        C[((size_t)(row + 8) * DIM + col) >> 1] =
            __floats2half2_rn(oacc[nt][2] * inv1, oacc[nt][3] * inv1);
    }
}

// ---------------- launch ----------------
extern "C" void kernel_launch(void* const* d_in, const int* in_sizes, int n_in,
                              void* d_out, int out_size) {
    const float* x       = (const float*)d_in[0];
    const float* n1g     = (const float*)d_in[1];
    const float* n1b     = (const float*)d_in[2];
    const float* qkv_w   = (const float*)d_in[3];
    const float* qkv_b   = (const float*)d_in[4];
    const float* proj_w  = (const float*)d_in[5];
    const float* proj_b  = (const float*)d_in[6];
    const float* n2g     = (const float*)d_in[7];
    const float* n2b     = (const float*)d_in[8];
    const float* fc1_w   = (const float*)d_in[9];
    const float* fc1_b   = (const float*)d_in[10];
    const float* fc2_w   = (const float*)d_in[11];
    const float* fc2_b   = (const float*)d_in[12];
    float* out = (float*)d_out;

    __half *h1h, *h2h, *olinh, *h3h, *qkvh, *qkvwh, *projwh, *fc1wh, *fc2wh;
    float *x2;
    cudaGetSymbolAddress((void**)&h1h,    g_h1h);
    cudaGetSymbolAddress((void**)&h2h,    g_h2h);
    cudaGetSymbolAddress((void**)&olinh,  g_olinh);
    cudaGetSymbolAddress((void**)&h3h,    g_h3h);
    cudaGetSymbolAddress((void**)&qkvh,   g_qkvh);
    cudaGetSymbolAddress((void**)&x2,     g_x2);
    cudaGetSymbolAddress((void**)&qkvwh,  g_qkvwh);
    cudaGetSymbolAddress((void**)&projwh, g_projwh);
    cudaGetSymbolAddress((void**)&fc1wh,  g_fc1wh);
    cudaGetSymbolAddress((void**)&fc2wh,  g_fc2wh);

    cudaFuncSetAttribute(hgemm_tn_kernel<EPI_BIAS, 1>,
                         cudaFuncAttributeMaxDynamicSharedMemorySize, GEMM_SMEM);
    cudaFuncSetAttribute(hgemm_tn_kernel<EPI_BIAS_RES, 0>,
                         cudaFuncAttributeMaxDynamicSharedMemorySize, GEMM_SMEM);
    cudaFuncSetAttribute(hgemm_tn_kernel<EPI_BIAS_GELU, 1>,
                         cudaFuncAttributeMaxDynamicSharedMemorySize, GEMM_SMEM);
    cudaFuncSetAttribute(flash_kernel,
                         cudaFuncAttributeMaxDynamicSharedMemorySize, FLASH_SMEM);

    // 0) all weights fp32 -> fp16, one launch
    const int n0 = QKVDIM*DIM/4, n1 = DIM*DIM/4, n2 = HIDDEN*DIM/4, n3 = DIM*HIDDEN/4;
    cvt_all<<<(n0+n1+n2+n3 + 255)/256, 256>>>(
        (const float4*)qkv_w,  (__half2*)qkvwh,  n0,
        (const float4*)proj_w, (__half2*)projwh, n1,
        (const float4*)fc1_w,  (__half2*)fc1wh,  n2,
        (const float4*)fc2_w,  (__half2*)fc2wh,  n3);

    // 1) LN1 -> fp16
    ln_kernel<<<TOK, 256>>>(x, n1g, n1b, h1h);
    // 2) QKV = h1 @ qkv_w^T + b  (fp16 out)
    hgemm_tn_kernel<EPI_BIAS, 1><<<dim3(QKVDIM/128, TOK/128), 256, GEMM_SMEM>>>(
        h1h, DIM, qkvwh, DIM, qkvh, QKVDIM, DIM, qkv_b, nullptr, 0);
    // 3) fused fp16 attention -> olin (fp16)
    flash_kernel<<<dim3(SEQ/128, NBH), 256, FLASH_SMEM>>>(qkvh, olinh);
    // 4) x2 = x + olin @ proj_w^T + b (fp32)
    hgemm_tn_kernel<EPI_BIAS_RES, 0><<<dim3(DIM/128, TOK/128), 256, GEMM_SMEM>>>(
        olinh, DIM, projwh, DIM, x2, DIM, DIM, proj_b, x, DIM);
    // 5) LN2 -> fp16
    ln_kernel<<<TOK, 256>>>(x2, n2g, n2b, h2h);
    // 6) h3 = gelu(h2 @ fc1_w^T + b) (fp16 out)
    hgemm_tn_kernel<EPI_BIAS_GELU, 1><<<dim3(HIDDEN/128, TOK/128), 256, GEMM_SMEM>>>(
        h2h, DIM, fc1wh, DIM, h3h, HIDDEN, DIM, fc1_b, nullptr, 0);
    // 7) out = x2 + h3 @ fc2_w^T + b (fp32)
    hgemm_tn_kernel<EPI_BIAS_RES, 0><<<dim3(DIM/128, TOK/128), 256, GEMM_SMEM>>>(
        h3h, HIDDEN, fc2wh, HIDDEN, out, DIM, HIDDEN, fc2_b, x2, DIM);
}